// round 12
// baseline (speedup 1.0000x reference)
#include <cuda_runtime.h>
#include <cuda_bf16.h>
#include <math.h>
#include <stdint.h>

#define NTOK  65536
#define NMEN  512
#define SQ    128
#define HD    768
#define TT    34

#define LOGITS_OFF 1
#define LBL_OFF    (1 + (NTOK + 2) * TT)
#define STE_OFF    (LBL_OFF + NTOK + 2)

// ---------------- scratch ----------------
__device__ __nv_bfloat16 g_xbf[(size_t)NTOK * HD];   // bf16 copy of X
__device__ __nv_bfloat16 g_wt[HD * HD];              // W transposed [j][k], bf16
__device__ float g_mlT[HD * TT];                     // mat_local transposed [h][t]
__device__ float g_cwH[40 * HD];                     // clsw^T hi (tf32)
__device__ float g_cwL[40 * HD];                     // clsw^T lo
__device__ float g_lws[HD * HD];                     // lin_w[:H] + lin_w[H:]
__device__ float g_scoreP[6 * NTOK];                 // partial scores per j-tile
__device__ float g_td[NTOK];
__device__ float g_head[NMEN * HD];
__device__ float g_z[NMEN * HD];
__device__ float g_zc[NMEN * TT];
__device__ float g_zml[NMEN * TT];
__device__ float g_lc[TT];
__device__ float g_lml[TT];
__device__ int   g_pred[NTOK];
__device__ float g_red[8];      // 0 hinge, 1 nll, 2 E_lbl_loc, 3 E_pred_loc, 4 n_valid
__device__ float g_histApred[TT], g_histBpred[TT];
__device__ float g_histAlbl[TT],  g_histBlbl[TT];

__device__ __forceinline__ float fast_tanh(float x) {
    float y; asm("tanh.approx.f32 %0, %1;" : "=f"(y) : "f"(x)); return y;
}

__device__ __forceinline__ void mma16816(float* c, const uint32_t* a,
                                         uint32_t b0, uint32_t b1) {
    asm volatile(
        "mma.sync.aligned.m16n8k16.row.col.f32.bf16.bf16.f32 "
        "{%0,%1,%2,%3}, {%4,%5,%6,%7}, {%8,%9}, {%0,%1,%2,%3};"
        : "+f"(c[0]), "+f"(c[1]), "+f"(c[2]), "+f"(c[3])
        : "r"(a[0]), "r"(a[1]), "r"(a[2]), "r"(a[3]), "r"(b0), "r"(b1));
}

__device__ __forceinline__ void mma_tf32(float* c, const uint32_t* a,
                                         uint32_t b0, uint32_t b1) {
    asm volatile(
        "mma.sync.aligned.m16n8k8.row.col.f32.tf32.tf32.f32 "
        "{%0,%1,%2,%3}, {%4,%5,%6,%7}, {%8,%9}, {%0,%1,%2,%3};"
        : "+f"(c[0]), "+f"(c[1]), "+f"(c[2]), "+f"(c[3])
        : "r"(a[0]), "r"(a[1]), "r"(a[2]), "r"(a[3]), "r"(b0), "r"(b1));
}

__device__ __forceinline__ void ldsm_x4(uint32_t& r0, uint32_t& r1,
                                        uint32_t& r2, uint32_t& r3, uint32_t addr) {
    asm volatile("ldmatrix.sync.aligned.m8n8.x4.shared.b16 {%0,%1,%2,%3}, [%4];"
                 : "=r"(r0), "=r"(r1), "=r"(r2), "=r"(r3) : "r"(addr));
}

__device__ __forceinline__ uint32_t cvt_tf32(float f) {
    uint32_t r; asm("cvt.rna.tf32.f32 %0, %1;" : "=r"(r) : "f"(f)); return r;
}

__device__ __forceinline__ void cp_async16(uint32_t dst, const void* src) {
    asm volatile("cp.async.ca.shared.global [%0], [%1], 16;"
                 :: "r"(dst), "l"(src));
}
#define CP_COMMIT() asm volatile("cp.async.commit_group;" ::: "memory")
#define CP_WAIT(n)  asm volatile("cp.async.wait_group %0;" :: "n"(n) : "memory")

// ============ C1: X fp32 -> bf16 ==========================================
__global__ __launch_bounds__(512) void c1_cvt(const float* __restrict__ X)
{
    size_t i = ((size_t)blockIdx.x * 512 + threadIdx.x) * 8;
    float4 a = *(const float4*)(X + i);
    float4 b = *(const float4*)(X + i + 4);
    __nv_bfloat162 h0 = __float22bfloat162_rn(make_float2(a.x, a.y));
    __nv_bfloat162 h1 = __float22bfloat162_rn(make_float2(a.z, a.w));
    __nv_bfloat162 h2 = __float22bfloat162_rn(make_float2(b.x, b.y));
    __nv_bfloat162 h3 = __float22bfloat162_rn(make_float2(b.z, b.w));
    uint4 o;
    o.x = *(uint32_t*)&h0; o.y = *(uint32_t*)&h1;
    o.z = *(uint32_t*)&h2; o.w = *(uint32_t*)&h3;
    *(uint4*)(g_xbf + i) = o;
}

// ============ C2: W transpose -> bf16 =====================================
__global__ void c2_wt(const float* __restrict__ W)
{
    __shared__ float t[32][33];
    int j0 = blockIdx.x * 32, k0 = blockIdx.y * 32;
    int tx = threadIdx.x, ty = threadIdx.y;
    #pragma unroll
    for (int q = 0; q < 32; q += 8)
        t[ty + q][tx] = W[(size_t)(k0 + ty + q) * HD + j0 + tx];
    __syncthreads();
    #pragma unroll
    for (int q = 0; q < 32; q += 8)
        g_wt[(size_t)(j0 + ty + q) * HD + k0 + tx] = __float2bfloat16(t[tx][ty + q]);
}

// ============ CM: lwsum + mat_local transpose + clsw tf32 hi/lo ===========
__global__ __launch_bounds__(256) void cM(
    const float* __restrict__ ml, const float* __restrict__ clsw,
    const float* __restrict__ lw)
{
    int i = blockIdx.x * 256 + threadIdx.x;          // 0 .. 589823
    g_lws[i] = lw[i] + lw[i + HD * HD];
    if (i < 40 * HD) {
        int t = i / HD, k = i - t * HD;
        float v = (t < TT) ? clsw[(size_t)k * TT + t] : 0.f;
        uint32_t hi = cvt_tf32(v);
        g_cwH[i] = __uint_as_float(hi);
        g_cwL[i] = __uint_as_float(cvt_tf32(v - __uint_as_float(hi)));
    }
    if (i < HD * TT) {
        int h = i / TT, t = i - h * TT;
        g_mlT[i] = ml[(size_t)t * HD + h];
    }
}

// ============ K1: HMMA partial score GEMM — 4x2 warp grid =================
// Warp (wm, wn): rows [wm*32, wm*32+32) x cols [wn*64, wn*64+64).
// Halves per-warp B ldmatrix traffic vs 8x1 layout.
#define ASTR 72
#define TILE_BF (128 * ASTR)

__global__ __launch_bounds__(256, 2) void k1_mma(
    const float* __restrict__ Wb, const float* __restrict__ vw)
{
    extern __shared__ __nv_bfloat16 sm[];
    __nv_bfloat16* As = sm;
    __nv_bfloat16* Bs = sm + 2 * TILE_BF;
    __shared__ float scsum[SQ];

    const int tid = threadIdx.x;
    const int w = tid >> 5, lane = tid & 31;
    const int wm = w & 3, wn = w >> 2;
    const int g = lane >> 2, tg = lane & 3;
    const int n = blockIdx.x, jp = blockIdx.y;

    if (tid < SQ) scsum[tid] = 0.f;

    const __nv_bfloat16* Abase = g_xbf + (size_t)n * SQ * HD;
    const __nv_bfloat16* Bbase = g_wt + (size_t)jp * 128 * HD;

    const uint32_t as_u = (uint32_t)__cvta_generic_to_shared(As);
    const uint32_t bs_u = (uint32_t)__cvta_generic_to_shared(Bs);

    const int lr = tid >> 3, lf = tid & 7;

    #pragma unroll
    for (int q = 0; q < 4; q++) {
        int r = lr + q * 32;
        uint32_t off = (uint32_t)(r * ASTR + lf * 8) * 2;
        cp_async16(as_u + off, Abase + (size_t)r * HD + lf * 8);
        cp_async16(bs_u + off, Bbase + (size_t)r * HD + lf * 8);
    }
    CP_COMMIT();

    float c[2][8][4];
    #pragma unroll
    for (int mi = 0; mi < 2; mi++)
        #pragma unroll
        for (int ni = 0; ni < 8; ni++)
            #pragma unroll
            for (int q = 0; q < 4; q++) c[mi][ni][q] = 0.f;

    const uint32_t a_lrow = (uint32_t)(lane & 15);
    const uint32_t a_koff = (uint32_t)((lane >> 4) * 8);
    const uint32_t b_jrow = (uint32_t)(((lane >> 4) << 3) + (lane & 7));
    const uint32_t b_koff = (uint32_t)(((lane >> 3) & 1) * 8);

    for (int kc = 0; kc < 12; kc++) {
        const int buf = kc & 1;
        if (kc + 1 < 12) {
            const int nb = (kc + 1) & 1;
            #pragma unroll
            for (int q = 0; q < 4; q++) {
                int r = lr + q * 32;
                uint32_t off = (uint32_t)(nb * TILE_BF + r * ASTR + lf * 8) * 2;
                cp_async16(as_u + off, Abase + (size_t)r * HD + (kc + 1) * 64 + lf * 8);
                cp_async16(bs_u + off, Bbase + (size_t)r * HD + (kc + 1) * 64 + lf * 8);
            }
            CP_COMMIT();
            CP_WAIT(1);
        } else {
            CP_WAIT(0);
        }
        __syncthreads();

        const uint32_t ab_u = as_u + (uint32_t)(buf * TILE_BF) * 2;
        const uint32_t bb_u = bs_u + (uint32_t)(buf * TILE_BF) * 2;
        #pragma unroll
        for (int ks = 0; ks < 4; ks++) {
            uint32_t a[2][4];
            #pragma unroll
            for (int mi = 0; mi < 2; mi++)
                ldsm_x4(a[mi][0], a[mi][1], a[mi][2], a[mi][3],
                        ab_u + (uint32_t)((wm * 32 + mi * 16 + a_lrow) * ASTR
                                          + ks * 16 + a_koff) * 2);
            #pragma unroll
            for (int p = 0; p < 4; p++) {
                uint32_t b0, b1, b2, b3;
                ldsm_x4(b0, b1, b2, b3,
                        bb_u + (uint32_t)((wn * 64 + p * 16 + b_jrow) * ASTR
                                          + ks * 16 + b_koff) * 2);
                mma16816(c[0][2 * p],     a[0], b0, b1);
                mma16816(c[0][2 * p + 1], a[0], b2, b3);
                mma16816(c[1][2 * p],     a[1], b0, b1);
                mma16816(c[1][2 * p + 1], a[1], b2, b3);
            }
        }
        __syncthreads();
    }

    // epilogue: partial score = sum_j tanh(h + Wb) * vw  (per-row, 64 cols)
    float s0 = 0.f, s1 = 0.f, s2 = 0.f, s3 = 0.f;
    #pragma unroll
    for (int ni = 0; ni < 8; ni++) {
        int j0 = jp * 128 + wn * 64 + ni * 8 + tg * 2;
        float w0 = __ldg(Wb + j0), w1 = __ldg(Wb + j0 + 1);
        float v0 = __ldg(vw + j0), v1 = __ldg(vw + j0 + 1);
        s0 += fast_tanh(c[0][ni][0] + w0) * v0 + fast_tanh(c[0][ni][1] + w1) * v1;
        s1 += fast_tanh(c[0][ni][2] + w0) * v0 + fast_tanh(c[0][ni][3] + w1) * v1;
        s2 += fast_tanh(c[1][ni][0] + w0) * v0 + fast_tanh(c[1][ni][1] + w1) * v1;
        s3 += fast_tanh(c[1][ni][2] + w0) * v0 + fast_tanh(c[1][ni][3] + w1) * v1;
    }
    #pragma unroll
    for (int o = 1; o <= 2; o <<= 1) {
        s0 += __shfl_xor_sync(~0u, s0, o);
        s1 += __shfl_xor_sync(~0u, s1, o);
        s2 += __shfl_xor_sync(~0u, s2, o);
        s3 += __shfl_xor_sync(~0u, s3, o);
    }
    if (tg == 0) {
        atomicAdd(&scsum[wm * 32 + g],      s0);
        atomicAdd(&scsum[wm * 32 + 8 + g],  s1);
        atomicAdd(&scsum[wm * 32 + 16 + g], s2);
        atomicAdd(&scsum[wm * 32 + 24 + g], s3);
    }
    __syncthreads();
    if (tid < SQ)
        g_scoreP[(size_t)jp * NTOK + n * SQ + tid] = scsum[tid];
}

// ============ K2: sum partials + softmax + head (bf16 X) ===================
__global__ __launch_bounds__(192) void k2_softmax_head()
{
    const int n = blockIdx.x;
    const int tid = threadIdx.x;
    const int lane = tid & 31, w = tid >> 5;
    __shared__ float sc[SQ];
    __shared__ float wr[8];

    float score = 0.f;
    if (tid < SQ) {
        #pragma unroll
        for (int p = 0; p < 6; p++)
            score += g_scoreP[(size_t)p * NTOK + n * SQ + tid];
    }
    if (tid < SQ) {
        float m = score;
        #pragma unroll
        for (int o = 16; o > 0; o >>= 1) m = fmaxf(m, __shfl_xor_sync(~0u, m, o));
        if (lane == 0) wr[w] = m;
    }
    __syncthreads();
    if (tid == 0) wr[4] = fmaxf(fmaxf(wr[0], wr[1]), fmaxf(wr[2], wr[3]));
    __syncthreads();
    float e = 0.f;
    if (tid < SQ) {
        e = __expf(score - wr[4]);
        float es = e;
        #pragma unroll
        for (int o = 16; o > 0; o >>= 1) es += __shfl_xor_sync(~0u, es, o);
        if (lane == 0) wr[w] = es;
    }
    __syncthreads();
    if (tid == 0) wr[5] = wr[0] + wr[1] + wr[2] + wr[3];
    __syncthreads();
    if (tid < SQ) {
        float td = e / wr[5];
        g_td[n * SQ + tid] = td;
        sc[tid] = td;
    }
    __syncthreads();

    const __nv_bfloat16* Xn = g_xbf + (size_t)n * SQ * HD;
    const int h0 = tid * 4;
    float a0 = 0.f, a1 = 0.f, a2 = 0.f, a3 = 0.f;
    #pragma unroll 4
    for (int s = 0; s < SQ; s++) {
        uint2 u = *(const uint2*)(Xn + (size_t)s * HD + h0);
        __nv_bfloat162 p0 = *(__nv_bfloat162*)&u.x;
        __nv_bfloat162 p1 = *(__nv_bfloat162*)&u.y;
        float t = sc[s];
        a0 += t * __bfloat162float(p0.x);
        a1 += t * __bfloat162float(p0.y);
        a2 += t * __bfloat162float(p1.x);
        a3 += t * __bfloat162float(p1.y);
    }
    float* hd = g_head + (size_t)n * HD + h0;
    hd[0] = a0; hd[1] = a1; hd[2] = a2; hd[3] = a3;
}

// ============ K3: z = head @ lwsum =========================================
__global__ __launch_bounds__(256) void k3_z()
{
    const int nb = blockIdx.x;
    const int cb = blockIdx.y;
    const int tid = threadIdx.x;
    __shared__ float hs[8 * HD];
    for (int i = tid; i < 8 * HD; i += 256)
        hs[i] = g_head[(size_t)nb * 8 * HD + i];
    __syncthreads();
    const int col = cb * 256 + tid;
    float acc[8] = {0, 0, 0, 0, 0, 0, 0, 0};
    for (int h = 0; h < HD; h++) {
        float w = g_lws[(size_t)h * HD + col];
        #pragma unroll
        for (int q = 0; q < 8; q++) acc[q] += hs[q * HD + h] * w;
    }
    #pragma unroll
    for (int q = 0; q < 8; q++)
        g_z[(size_t)(nb * 8 + q) * HD + col] = acc[q];
}

// ============ K4: zc/zml (4 mentions/block); lc/lml/hists in last block ===
__global__ __launch_bounds__(272) void k4_small(
    const float* __restrict__ clsw, const float* __restrict__ linb,
    const int* __restrict__ labels)
{
    const int tid = threadIdx.x;
    if (blockIdx.x < 128) {
        __shared__ float zs[4 * HD];
        for (int i = tid; i < 4 * HD; i += 272)
            zs[i] = g_z[(size_t)blockIdx.x * 4 * HD + i];
        __syncthreads();
        const int g = tid / 68, t = tid - g * 68;
        const int b = blockIdx.x * 4 + g;
        const float* z = zs + g * HD;
        if (t < TT) {
            float a = 0.f;
            for (int h = 0; h < HD; h++) a += z[h] * clsw[h * TT + t];
            g_zc[b * TT + t] = a;
        } else {
            int tt = t - TT;
            float a = 0.f;
            for (int h = 0; h < HD; h++) a += z[h] * g_mlT[h * TT + tt];
            g_zml[b * TT + tt] = a;
        }
    } else {
        if (tid < TT) {
            float a = 0.f, c = 0.f;
            for (int h = 0; h < HD; h++) {
                float lb = linb[h];
                a += lb * clsw[h * TT + tid];
                c += lb * g_mlT[h * TT + tid];
            }
            g_lc[tid] = a; g_lml[tid] = c;
            float ha = 0.f, hb = 0.f;
            for (int nn = 0; nn < NMEN; nn++) {
                ha += (labels[nn * SQ + (SQ - 2)] == tid) ? 1.f : 0.f;
                hb += (labels[nn * SQ + (SQ - 1)] == tid) ? 1.f : 0.f;
            }
            g_histAlbl[tid] = ha; g_histBlbl[tid] = hb;
            g_histApred[tid] = 0.f; g_histBpred[tid] = 0.f;
        }
        if (tid >= TT && tid < TT + 8) g_red[tid - TT] = 0.f;
    }
}

// ============ K5: 3xTF32 logits GEMM + relu + outputs + hinge/CE/pred =====
#define XSTR 36
#define XS_TILE (128 * XSTR)
#define WS_TILE (40 * XSTR)

__global__ __launch_bounds__(128) void k5_logits(
    const float* __restrict__ X, const float* __restrict__ clsb,
    const int* __restrict__ labels, const int* __restrict__ padp,
    float* __restrict__ out)
{
    extern __shared__ float dyn[];
    float* Xs = dyn;                        // [2][128*36]
    float* Wh = dyn + 2 * XS_TILE;          // [2][40*36]
    float* Wl = Wh + 2 * WS_TILE;
    float* Gs = dyn;                        // reuse

    __shared__ float td_s[SQ];
    __shared__ float zc_s[TT], lc_s[TT], cb_s[TT];
    __shared__ float rh[4], rn[4], rv[4];

    const int n = blockIdx.x;
    const int tid = threadIdx.x;
    const int w = tid >> 5, lane = tid & 31;
    const int g = lane >> 2, tg = lane & 3;
    const int pad = padp[0];

    td_s[tid] = g_td[n * SQ + tid];
    if (tid < TT) {
        zc_s[tid] = g_zc[n * TT + tid];
        lc_s[tid] = g_lc[tid];
        cb_s[tid] = clsb[tid];
    }

    const float* Xbase = X + (size_t)n * SQ * HD;
    const uint32_t xs_u = (uint32_t)__cvta_generic_to_shared(Xs);
    const uint32_t wh_u = (uint32_t)__cvta_generic_to_shared(Wh);
    const uint32_t wl_u = (uint32_t)__cvta_generic_to_shared(Wl);

    #pragma unroll
    for (int f = 0; f < 8; f++)
        cp_async16(xs_u + (uint32_t)(tid * XSTR + f * 4) * 4,
                   Xbase + (size_t)tid * HD + f * 4);
    for (int idx = tid; idx < 320; idx += 128) {
        int r = idx >> 3, f = idx & 7;
        cp_async16(wh_u + (uint32_t)(r * XSTR + f * 4) * 4,
                   g_cwH + (size_t)r * HD + f * 4);
        cp_async16(wl_u + (uint32_t)(r * XSTR + f * 4) * 4,
                   g_cwL + (size_t)r * HD + f * 4);
    }
    CP_COMMIT();

    float acc[2][5][4];
    #pragma unroll
    for (int mt = 0; mt < 2; mt++)
        #pragma unroll
        for (int ni = 0; ni < 5; ni++)
            #pragma unroll
            for (int q = 0; q < 4; q++) acc[mt][ni][q] = 0.f;

    for (int kc = 0; kc < 24; kc++) {
        const int buf = kc & 1;
        if (kc + 1 < 24) {
            const int nb = (kc + 1) & 1;
            #pragma unroll
            for (int f = 0; f < 8; f++)
                cp_async16(xs_u + (uint32_t)(nb * XS_TILE + tid * XSTR + f * 4) * 4,
                           Xbase + (size_t)tid * HD + (kc + 1) * 32 + f * 4);
            for (int idx = tid; idx < 320; idx += 128) {
                int r = idx >> 3, f = idx & 7;
                cp_async16(wh_u + (uint32_t)(nb * WS_TILE + r * XSTR + f * 4) * 4,
                           g_cwH + (size_t)r * HD + (kc + 1) * 32 + f * 4);
                cp_async16(wl_u + (uint32_t)(nb * WS_TILE + r * XSTR + f * 4) * 4,
                           g_cwL + (size_t)r * HD + (kc + 1) * 32 + f * 4);
            }
            CP_COMMIT();
            CP_WAIT(1);
        } else {
            CP_WAIT(0);
        }
        __syncthreads();

        const float* Xb  = Xs + buf * XS_TILE;
        const float* Whb = Wh + buf * WS_TILE;
        const float* Wlb = Wl + buf * WS_TILE;
        #pragma unroll
        for (int ks = 0; ks < 4; ks++) {
            const int k8 = ks * 8;
            uint32_t ah[2][4], al[2][4];
            #pragma unroll
            for (int mt = 0; mt < 2; mt++) {
                int rb = w * 32 + mt * 16 + g;
                float x0 = Xb[rb * XSTR + k8 + tg];
                float x1 = Xb[(rb + 8) * XSTR + k8 + tg];
                float x2 = Xb[rb * XSTR + k8 + tg + 4];
                float x3 = Xb[(rb + 8) * XSTR + k8 + tg + 4];
                ah[mt][0] = cvt_tf32(x0);
                ah[mt][1] = cvt_tf32(x1);
                ah[mt][2] = cvt_tf32(x2);
                ah[mt][3] = cvt_tf32(x3);
                al[mt][0] = cvt_tf32(x0 - __uint_as_float(ah[mt][0]));
                al[mt][1] = cvt_tf32(x1 - __uint_as_float(ah[mt][1]));
                al[mt][2] = cvt_tf32(x2 - __uint_as_float(ah[mt][2]));
                al[mt][3] = cvt_tf32(x3 - __uint_as_float(ah[mt][3]));
            }
            #pragma unroll
            for (int ni = 0; ni < 5; ni++) {
                uint32_t bh0 = __float_as_uint(Whb[(ni * 8 + g) * XSTR + k8 + tg]);
                uint32_t bh1 = __float_as_uint(Whb[(ni * 8 + g) * XSTR + k8 + tg + 4]);
                uint32_t bl0 = __float_as_uint(Wlb[(ni * 8 + g) * XSTR + k8 + tg]);
                uint32_t bl1 = __float_as_uint(Wlb[(ni * 8 + g) * XSTR + k8 + tg + 4]);
                #pragma unroll
                for (int mt = 0; mt < 2; mt++) {
                    mma_tf32(acc[mt][ni], al[mt], bh0, bh1);
                    mma_tf32(acc[mt][ni], ah[mt], bl0, bl1);
                    mma_tf32(acc[mt][ni], ah[mt], bh0, bh1);
                }
            }
        }
        __syncthreads();
    }

    #pragma unroll
    for (int mt = 0; mt < 2; mt++)
        #pragma unroll
        for (int ni = 0; ni < 5; ni++)
            #pragma unroll
            for (int q = 0; q < 4; q++) {
                int r = w * 32 + mt * 16 + g + ((q >= 2) ? 8 : 0);
                int t = ni * 8 + tg * 2 + (q & 1);
                if (t < TT) {
                    float lg = fmaxf(acc[mt][ni][q] + td_s[r] * zc_s[t]
                                     + lc_s[t] + cb_s[t], 0.f);
                    Gs[r * 35 + t] = lg;
                    long gtok = (long)n * SQ + r;
                    out[LOGITS_OFF + (gtok + 1) * TT + t] = lg;
                    if (gtok == 0)        out[LOGITS_OFF + t] = lg;
                    if (gtok == NTOK - 1) out[LOGITS_OFF + (long)(NTOK + 1) * TT + t] = lg;
                }
            }
    __syncthreads();

    const int r = tid;
    const long gtok = (long)n * SQ + r;
    const int lbl = labels[gtok];
    const bool valid = (lbl != pad);
    const float* Lr = &Gs[r * 35];

    float mx = Lr[0]; int am = 0;
    #pragma unroll
    for (int t = 1; t < TT; t++) { float l = Lr[t]; if (l > mx) { mx = l; am = t; } }
    float se = 0.f;
    #pragma unroll
    for (int t = 0; t < TT; t++) se += __expf(Lr[t] - mx);
    float lse = mx + logf(se);
    float sy = Lr[lbl];
    float so = -1e30f;
    #pragma unroll
    for (int t = 0; t < TT; t++) if (t != lbl) so = fmaxf(so, Lr[t]);

    float hinge = valid ? fmaxf(0.f, 1.f + so - sy) : 0.f;
    float nll   = valid ? (lse - sy) : 0.f;
    float nv    = valid ? 1.f : 0.f;

    g_pred[gtok] = am;
    out[LBL_OFF + gtok + 1] = (float)lbl;
    if (gtok == 0)        out[LBL_OFF] = (float)lbl;
    if (gtok == NTOK - 1) out[LBL_OFF + NTOK + 1] = (float)lbl;

    if (r == SQ - 2) atomicAdd(&g_histApred[am], 1.f);
    if (r == SQ - 1) atomicAdd(&g_histBpred[am], 1.f);

    for (int o = 16; o > 0; o >>= 1) {
        hinge += __shfl_xor_sync(~0u, hinge, o);
        nll   += __shfl_xor_sync(~0u, nll, o);
        nv    += __shfl_xor_sync(~0u, nv, o);
    }
    if (lane == 0) { rh[w] = hinge; rn[w] = nll; rv[w] = nv; }
    __syncthreads();
    if (tid == 0) {
        float H = 0, N2 = 0, V = 0;
        for (int q = 0; q < 4; q++) { H += rh[q]; N2 += rn[q]; V += rv[q]; }
        atomicAdd(&g_red[0], H);
        atomicAdd(&g_red[1], N2);
        atomicAdd(&g_red[4], V);
    }
}

// ============ K6: energy local dots + ste (float4 vectorized) =============
__global__ __launch_bounds__(192) void k6_energy_ste(
    const float* __restrict__ X, const float* __restrict__ ml,
    const float* __restrict__ linb, const int* __restrict__ labels,
    const int* __restrict__ padp, float* __restrict__ out)
{
    __shared__ int lbl_s[SQ], pred_s[SQ];
    __shared__ float td_s[SQ];
    __shared__ float s_cnt, s_tdm, s_dL, s_dP;
    const int n = blockIdx.x, tid = threadIdx.x;
    const int lane = tid & 31;
    const int pad = padp[0];

    if (tid == 0) { s_cnt = 0.f; s_tdm = 0.f; s_dL = 0.f; s_dP = 0.f; }
    if (tid < SQ) {
        lbl_s[tid]  = labels[n * SQ + tid];
        pred_s[tid] = g_pred[n * SQ + tid];
        td_s[tid]   = g_td[n * SQ + tid];
    }
    __syncthreads();

    float cnt_p = 0.f, tdm_p = 0.f, dotL = 0.f, dotP = 0.f;
    if (tid < SQ) {
        int l = lbl_s[tid], p = pred_s[tid];
        float m = (p != pad) ? 1.f : 0.f;
        cnt_p = m; tdm_p = m * td_s[tid];
        dotL = td_s[tid] * g_zml[n * TT + l] + g_lml[l];
        dotP = td_s[tid] * g_zml[n * TT + p] + g_lml[p];
    }

    const int h0 = tid * 4;
    const float* Xn = X + (size_t)n * SQ * HD;
    float st0 = 0.f, st1 = 0.f, st2 = 0.f, st3 = 0.f;
    for (int s = 0; s < SQ; s++) {
        float4 x4 = *(const float4*)(Xn + (size_t)s * HD + h0);
        int l = lbl_s[s], p = pred_s[s];
        float4 mL = *(const float4*)(ml + (size_t)l * HD + h0);
        float4 mP = *(const float4*)(ml + (size_t)p * HD + h0);
        dotL += x4.x * mL.x + x4.y * mL.y + x4.z * mL.z + x4.w * mL.w;
        dotP += x4.x * mP.x + x4.y * mP.y + x4.z * mP.z + x4.w * mP.w;
        if (p != pad) { st0 += x4.x; st1 += x4.y; st2 += x4.z; st3 += x4.w; }
    }

    for (int o = 16; o > 0; o >>= 1) {
        cnt_p += __shfl_xor_sync(~0u, cnt_p, o);
        tdm_p += __shfl_xor_sync(~0u, tdm_p, o);
        dotL  += __shfl_xor_sync(~0u, dotL, o);
        dotP  += __shfl_xor_sync(~0u, dotP, o);
    }
    if (lane == 0) {
        atomicAdd(&s_cnt, cnt_p);
        atomicAdd(&s_tdm, tdm_p);
        atomicAdd(&s_dL, dotL);
        atomicAdd(&s_dP, dotP);
    }
    __syncthreads();
    if (tid == 0) {
        atomicAdd(&g_red[2], s_dL);
        atomicAdd(&g_red[3], s_dP);
    }

    const float cnt = s_cnt, tdm = s_tdm;
    float o0 = 0.f, o1 = 0.f, o2 = 0.f, o3 = 0.f;
    if (cnt > 0.f) {
        const float* zp = g_z + (size_t)n * HD + h0;
        const float* lp = linb + h0;
        float inv = 1.f / cnt;
        o0 = (st0 + tdm * zp[0] + cnt * lp[0]) * inv;
        o1 = (st1 + tdm * zp[1] + cnt * lp[1]) * inv;
        o2 = (st2 + tdm * zp[2] + cnt * lp[2]) * inv;
        o3 = (st3 + tdm * zp[3] + cnt * lp[3]) * inv;
    }
    float* op = out + STE_OFF + (size_t)n * HD + h0;
    op[0] = o0; op[1] = o1; op[2] = o2; op[3] = o3;
}

// ============ K7: finalize scalar loss =====================================
__global__ void k7_final(const float* __restrict__ mlab, float* __restrict__ out)
{
    __shared__ float s1[TT], s2[TT];
    int t = threadIdx.x;
    if (t < TT) {
        float rl = 0.f, rp = 0.f;
        for (int u = 0; u < TT; u++) {
            float mv = mlab[t * TT + u];
            rl += mv * g_histBlbl[u];
            rp += mv * g_histBpred[u];
        }
        s1[t] = g_histAlbl[t] * rl;
        s2[t] = g_histApred[t] * rp;
    }
    __syncthreads();
    if (t == 0) {
        float labL = 0.f, labP = 0.f;
        for (int u = 0; u < TT; u++) { labL += s1[u]; labP += s2[u]; }
        float nv = fmaxf(g_red[4], 1.f);
        float hinge = g_red[0] / nv;
        float ce = g_red[1] / nv;
        float El = g_red[2] + labL;
        float Ep = g_red[3] + labP;
        float lte = fmaxf(0.f, hinge + El - Ep);
        out[0] = 1.0f * lte + 0.5f * ce;
    }
}

extern "C" void kernel_launch(void* const* d_in, const int* in_sizes, int n_in,
                              void* d_out, int out_size)
{
    const float* X      = (const float*)d_in[0];
    const int*   labels = (const int*)  d_in[1];
    const int*   padp   = (const int*)  d_in[4];
    const float* Ww     = (const float*)d_in[6];
    const float* Wb     = (const float*)d_in[7];
    const float* vw     = (const float*)d_in[8];
    const float* clsw   = (const float*)d_in[10];
    const float* clsb   = (const float*)d_in[11];
    const float* ml     = (const float*)d_in[12];
    const float* mlab   = (const float*)d_in[13];
    const float* lw     = (const float*)d_in[14];
    const float* linb   = (const float*)d_in[15];
    float* out = (float*)d_out;
    (void)in_sizes; (void)n_in; (void)out_size;

    const int k1_smem = 4 * TILE_BF * 2;                       // 73728 bytes
    const int k5_smem = (2 * XS_TILE + 4 * WS_TILE) * 4;       // 48384 bytes
    cudaFuncSetAttribute(k1_mma, cudaFuncAttributeMaxDynamicSharedMemorySize, k1_smem);
    cudaFuncSetAttribute(k5_logits, cudaFuncAttributeMaxDynamicSharedMemorySize, k5_smem);

    c1_cvt<<<12288, 512>>>(X);
    c2_wt<<<dim3(24, 24), dim3(32, 8)>>>(Ww);
    cM<<<2304, 256>>>(ml, clsw, lw);
    k1_mma<<<dim3(NMEN, 6), 256, k1_smem>>>(Wb, vw);
    k2_softmax_head<<<NMEN, 192>>>();
    k3_z<<<dim3(64, 3), 256>>>();
    k4_small<<<129, 272>>>(clsw, linb, labels);
    k5_logits<<<NMEN, 128, k5_smem>>>(X, clsb, labels, padp, out);
    k6_energy_ste<<<NMEN, 192>>>(X, ml, linb, labels, padp, out);
    k7_final<<<1, 64>>>(mlab, out);
}

// round 13
// speedup vs baseline: 1.0073x; 1.0073x over previous
#include <cuda_runtime.h>
#include <cuda_bf16.h>
#include <math.h>
#include <stdint.h>

#define NTOK  65536
#define NMEN  512
#define SQ    128
#define HD    768
#define TT    34

#define LOGITS_OFF 1
#define LBL_OFF    (1 + (NTOK + 2) * TT)
#define STE_OFF    (LBL_OFF + NTOK + 2)

// ---------------- scratch ----------------
__device__ __nv_bfloat16 g_xbf[(size_t)NTOK * HD];   // bf16 copy of X
__device__ __nv_bfloat16 g_wt[HD * HD];              // W transposed [j][k], bf16
__device__ float g_mlT[HD * TT];                     // mat_local transposed [h][t]
__device__ float g_cwH[40 * HD];                     // clsw^T hi (tf32)
__device__ float g_cwL[40 * HD];                     // clsw^T lo
__device__ float g_scoreP[6 * NTOK];                 // partial scores per j-tile
__device__ float g_td[NTOK];
__device__ float g_head[NMEN * HD];
__device__ float g_z[NMEN * HD];
__device__ float g_zc[NMEN * TT];
__device__ float g_zml[NMEN * TT];
__device__ float g_lc[TT];
__device__ float g_lml[TT];
__device__ int   g_pred[NTOK];
__device__ float g_red[8];      // 0 hinge, 1 nll, 2 E_lbl_loc, 3 E_pred_loc, 4 n_valid
__device__ float g_histApred[TT], g_histBpred[TT];
__device__ float g_histAlbl[TT],  g_histBlbl[TT];

__device__ __forceinline__ float fast_tanh(float x) {
    float y; asm("tanh.approx.f32 %0, %1;" : "=f"(y) : "f"(x)); return y;
}

__device__ __forceinline__ void mma16816(float* c, const uint32_t* a,
                                         uint32_t b0, uint32_t b1) {
    asm volatile(
        "mma.sync.aligned.m16n8k16.row.col.f32.bf16.bf16.f32 "
        "{%0,%1,%2,%3}, {%4,%5,%6,%7}, {%8,%9}, {%0,%1,%2,%3};"
        : "+f"(c[0]), "+f"(c[1]), "+f"(c[2]), "+f"(c[3])
        : "r"(a[0]), "r"(a[1]), "r"(a[2]), "r"(a[3]), "r"(b0), "r"(b1));
}

__device__ __forceinline__ void mma_tf32(float* c, const uint32_t* a,
                                         uint32_t b0, uint32_t b1) {
    asm volatile(
        "mma.sync.aligned.m16n8k8.row.col.f32.tf32.tf32.f32 "
        "{%0,%1,%2,%3}, {%4,%5,%6,%7}, {%8,%9}, {%0,%1,%2,%3};"
        : "+f"(c[0]), "+f"(c[1]), "+f"(c[2]), "+f"(c[3])
        : "r"(a[0]), "r"(a[1]), "r"(a[2]), "r"(a[3]), "r"(b0), "r"(b1));
}

__device__ __forceinline__ void ldsm_x4(uint32_t& r0, uint32_t& r1,
                                        uint32_t& r2, uint32_t& r3, uint32_t addr) {
    asm volatile("ldmatrix.sync.aligned.m8n8.x4.shared.b16 {%0,%1,%2,%3}, [%4];"
                 : "=r"(r0), "=r"(r1), "=r"(r2), "=r"(r3) : "r"(addr));
}

__device__ __forceinline__ uint32_t cvt_tf32(float f) {
    uint32_t r; asm("cvt.rna.tf32.f32 %0, %1;" : "=r"(r) : "f"(f)); return r;
}

__device__ __forceinline__ void cp_async16(uint32_t dst, const void* src) {
    asm volatile("cp.async.ca.shared.global [%0], [%1], 16;"
                 :: "r"(dst), "l"(src));
}
#define CP_COMMIT() asm volatile("cp.async.commit_group;" ::: "memory")
#define CP_WAIT(n)  asm volatile("cp.async.wait_group %0;" :: "n"(n) : "memory")

// ============ C1: X fp32 -> bf16 ==========================================
__global__ __launch_bounds__(512) void c1_cvt(const float* __restrict__ X)
{
    size_t i = ((size_t)blockIdx.x * 512 + threadIdx.x) * 8;
    float4 a = *(const float4*)(X + i);
    float4 b = *(const float4*)(X + i + 4);
    __nv_bfloat162 h0 = __float22bfloat162_rn(make_float2(a.x, a.y));
    __nv_bfloat162 h1 = __float22bfloat162_rn(make_float2(a.z, a.w));
    __nv_bfloat162 h2 = __float22bfloat162_rn(make_float2(b.x, b.y));
    __nv_bfloat162 h3 = __float22bfloat162_rn(make_float2(b.z, b.w));
    uint4 o;
    o.x = *(uint32_t*)&h0; o.y = *(uint32_t*)&h1;
    o.z = *(uint32_t*)&h2; o.w = *(uint32_t*)&h3;
    *(uint4*)(g_xbf + i) = o;
}

// ============ C2: W transpose -> bf16 =====================================
__global__ void c2_wt(const float* __restrict__ W)
{
    __shared__ float t[32][33];
    int j0 = blockIdx.x * 32, k0 = blockIdx.y * 32;
    int tx = threadIdx.x, ty = threadIdx.y;
    #pragma unroll
    for (int q = 0; q < 32; q += 8)
        t[ty + q][tx] = W[(size_t)(k0 + ty + q) * HD + j0 + tx];
    __syncthreads();
    #pragma unroll
    for (int q = 0; q < 32; q += 8)
        g_wt[(size_t)(j0 + ty + q) * HD + k0 + tx] = __float2bfloat16(t[tx][ty + q]);
}

// ============ C3: mat_local transpose =====================================
__global__ void c3_mlt(const float* __restrict__ ml)
{
    for (int i = threadIdx.x; i < HD * TT; i += blockDim.x) {
        int h = i / TT, t = i - h * TT;
        g_mlT[i] = ml[(size_t)t * HD + h];
    }
}

// ============ C4: clsw transpose (+pad to 40 rows), tf32 hi/lo ============
__global__ void c4_cwt(const float* __restrict__ clsw)
{
    int i = blockIdx.x * 256 + threadIdx.x;
    if (i < 40 * HD) {
        int t = i / HD, k = i - t * HD;
        float v = (t < TT) ? clsw[(size_t)k * TT + t] : 0.f;
        uint32_t hi = cvt_tf32(v);
        g_cwH[i] = __uint_as_float(hi);
        g_cwL[i] = __uint_as_float(cvt_tf32(v - __uint_as_float(hi)));
    }
}

// ============ K1: HMMA partial score GEMM (ldmatrix + cp.async) ===========
// grid (NMEN, 3): each CTA does TWO 128-col j-tiles back to back, so the
// second pass re-reads the A tile from L2 instead of DRAM (halves A traffic).
#define ASTR 72
#define TILE_BF (128 * ASTR)

__global__ __launch_bounds__(256, 2) void k1_mma(
    const float* __restrict__ Wb, const float* __restrict__ vw)
{
    extern __shared__ __nv_bfloat16 sm[];
    __nv_bfloat16* As = sm;
    __nv_bfloat16* Bs = sm + 2 * TILE_BF;

    const int tid = threadIdx.x;
    const int w = tid >> 5, lane = tid & 31;
    const int g = lane >> 2, tg = lane & 3;
    const int n = blockIdx.x;

    const __nv_bfloat16* Abase = g_xbf + (size_t)n * SQ * HD;

    const uint32_t as_u = (uint32_t)__cvta_generic_to_shared(As);
    const uint32_t bs_u = (uint32_t)__cvta_generic_to_shared(Bs);

    const int lr = tid >> 3, lf = tid & 7;

    const uint32_t a_lrow = (uint32_t)(lane & 15);
    const uint32_t a_koff = (uint32_t)((lane >> 4) * 8);
    const uint32_t b_jrow = (uint32_t)(((lane >> 4) << 3) + (lane & 7));
    const uint32_t b_koff = (uint32_t)(((lane >> 3) & 1) * 8);

    for (int half = 0; half < 2; half++) {
        const int jp = blockIdx.y * 2 + half;
        const __nv_bfloat16* Bbase = g_wt + (size_t)jp * 128 * HD;

        // preload chunk 0 into buffer 0
        #pragma unroll
        for (int q = 0; q < 4; q++) {
            int r = lr + q * 32;
            uint32_t off = (uint32_t)(r * ASTR + lf * 8) * 2;
            cp_async16(as_u + off, Abase + (size_t)r * HD + lf * 8);
            cp_async16(bs_u + off, Bbase + (size_t)r * HD + lf * 8);
        }
        CP_COMMIT();

        float c[16][4];
        #pragma unroll
        for (int ni = 0; ni < 16; ni++)
            #pragma unroll
            for (int q = 0; q < 4; q++) c[ni][q] = 0.f;

        for (int kc = 0; kc < 12; kc++) {
            const int buf = kc & 1;
            if (kc + 1 < 12) {
                const int nb = (kc + 1) & 1;
                #pragma unroll
                for (int q = 0; q < 4; q++) {
                    int r = lr + q * 32;
                    uint32_t off = (uint32_t)(nb * TILE_BF + r * ASTR + lf * 8) * 2;
                    cp_async16(as_u + off, Abase + (size_t)r * HD + (kc + 1) * 64 + lf * 8);
                    cp_async16(bs_u + off, Bbase + (size_t)r * HD + (kc + 1) * 64 + lf * 8);
                }
                CP_COMMIT();
                CP_WAIT(1);
            } else {
                CP_WAIT(0);
            }
            __syncthreads();

            const uint32_t ab_u = as_u + (uint32_t)(buf * TILE_BF) * 2;
            const uint32_t bb_u = bs_u + (uint32_t)(buf * TILE_BF) * 2;
            #pragma unroll
            for (int ks = 0; ks < 4; ks++) {
                uint32_t a[4];
                ldsm_x4(a[0], a[1], a[2], a[3],
                        ab_u + (uint32_t)((w * 16 + a_lrow) * ASTR + ks * 16 + a_koff) * 2);
                #pragma unroll
                for (int p = 0; p < 8; p++) {
                    uint32_t b0, b1, b2, b3;
                    ldsm_x4(b0, b1, b2, b3,
                            bb_u + (uint32_t)((p * 16 + b_jrow) * ASTR + ks * 16 + b_koff) * 2);
                    mma16816(c[2 * p],     a, b0, b1);
                    mma16816(c[2 * p + 1], a, b2, b3);
                }
            }
            __syncthreads();
        }

        float sco0 = 0.f, sco1 = 0.f;
        #pragma unroll
        for (int ni = 0; ni < 16; ni++) {
            int j0 = jp * 128 + ni * 8 + tg * 2;
            float w0 = __ldg(Wb + j0), w1 = __ldg(Wb + j0 + 1);
            float v0 = __ldg(vw + j0), v1 = __ldg(vw + j0 + 1);
            sco0 += fast_tanh(c[ni][0] + w0) * v0 + fast_tanh(c[ni][1] + w1) * v1;
            sco1 += fast_tanh(c[ni][2] + w0) * v0 + fast_tanh(c[ni][3] + w1) * v1;
        }
        sco0 += __shfl_xor_sync(~0u, sco0, 1);
        sco0 += __shfl_xor_sync(~0u, sco0, 2);
        sco1 += __shfl_xor_sync(~0u, sco1, 1);
        sco1 += __shfl_xor_sync(~0u, sco1, 2);
        if (tg == 0) {
            g_scoreP[(size_t)jp * NTOK + n * SQ + w * 16 + g]     = sco0;
            g_scoreP[(size_t)jp * NTOK + n * SQ + w * 16 + 8 + g] = sco1;
        }
        __syncthreads();
    }
}

// ============ K2: sum partials + softmax + head (bf16 X) ===================
__global__ __launch_bounds__(192) void k2_softmax_head()
{
    const int n = blockIdx.x;
    const int tid = threadIdx.x;
    const int lane = tid & 31, w = tid >> 5;
    __shared__ float sc[SQ];
    __shared__ float wr[8];

    float score = 0.f;
    if (tid < SQ) {
        #pragma unroll
        for (int p = 0; p < 6; p++)
            score += g_scoreP[(size_t)p * NTOK + n * SQ + tid];
    }
    if (tid < SQ) {
        float m = score;
        #pragma unroll
        for (int o = 16; o > 0; o >>= 1) m = fmaxf(m, __shfl_xor_sync(~0u, m, o));
        if (lane == 0) wr[w] = m;
    }
    __syncthreads();
    if (tid == 0) wr[4] = fmaxf(fmaxf(wr[0], wr[1]), fmaxf(wr[2], wr[3]));
    __syncthreads();
    float e = 0.f;
    if (tid < SQ) {
        e = __expf(score - wr[4]);
        float es = e;
        #pragma unroll
        for (int o = 16; o > 0; o >>= 1) es += __shfl_xor_sync(~0u, es, o);
        if (lane == 0) wr[w] = es;
    }
    __syncthreads();
    if (tid == 0) wr[5] = wr[0] + wr[1] + wr[2] + wr[3];
    __syncthreads();
    if (tid < SQ) {
        float td = e / wr[5];
        g_td[n * SQ + tid] = td;
        sc[tid] = td;
    }
    __syncthreads();

    const __nv_bfloat16* Xn = g_xbf + (size_t)n * SQ * HD;
    const int h0 = tid * 4;
    float a0 = 0.f, a1 = 0.f, a2 = 0.f, a3 = 0.f;
    #pragma unroll 4
    for (int s = 0; s < SQ; s++) {
        uint2 u = *(const uint2*)(Xn + (size_t)s * HD + h0);
        __nv_bfloat162 p0 = *(__nv_bfloat162*)&u.x;
        __nv_bfloat162 p1 = *(__nv_bfloat162*)&u.y;
        float t = sc[s];
        a0 += t * __bfloat162float(p0.x);
        a1 += t * __bfloat162float(p0.y);
        a2 += t * __bfloat162float(p1.x);
        a3 += t * __bfloat162float(p1.y);
    }
    float* hd = g_head + (size_t)n * HD + h0;
    hd[0] = a0; hd[1] = a1; hd[2] = a2; hd[3] = a3;
}

// ============ K3: z = head @ (lin_w[:H] + lin_w[H:]) =======================
__global__ __launch_bounds__(256) void k3_z(const float* __restrict__ lw)
{
    const int nb = blockIdx.x;
    const int cb = blockIdx.y;
    const int tid = threadIdx.x;
    __shared__ float hs[8 * HD];
    for (int i = tid; i < 8 * HD; i += 256)
        hs[i] = g_head[(size_t)nb * 8 * HD + i];
    __syncthreads();
    const int col = cb * 256 + tid;
    float acc[8] = {0, 0, 0, 0, 0, 0, 0, 0};
    for (int h = 0; h < HD; h++) {
        float w = lw[(size_t)h * HD + col] + lw[(size_t)(h + HD) * HD + col];
        #pragma unroll
        for (int q = 0; q < 8; q++) acc[q] += hs[q * HD + h] * w;
    }
    #pragma unroll
    for (int q = 0; q < 8; q++)
        g_z[(size_t)(nb * 8 + q) * HD + col] = acc[q];
}

// ============ K4: zc/zml (4 mentions/block); lc/lml/hists in last block ===
__global__ __launch_bounds__(272) void k4_small(
    const float* __restrict__ clsw, const float* __restrict__ linb,
    const int* __restrict__ labels)
{
    const int tid = threadIdx.x;
    if (blockIdx.x < 128) {
        __shared__ float zs[4 * HD];
        for (int i = tid; i < 4 * HD; i += 272)
            zs[i] = g_z[(size_t)blockIdx.x * 4 * HD + i];
        __syncthreads();
        const int g = tid / 68, t = tid - g * 68;
        const int b = blockIdx.x * 4 + g;
        const float* z = zs + g * HD;
        if (t < TT) {
            float a = 0.f;
            for (int h = 0; h < HD; h++) a += z[h] * clsw[h * TT + t];
            g_zc[b * TT + t] = a;
        } else {
            int tt = t - TT;
            float a = 0.f;
            for (int h = 0; h < HD; h++) a += z[h] * g_mlT[h * TT + tt];
            g_zml[b * TT + tt] = a;
        }
    } else {
        if (tid < TT) {
            float a = 0.f, c = 0.f;
            for (int h = 0; h < HD; h++) {
                float lb = linb[h];
                a += lb * clsw[h * TT + tid];
                c += lb * g_mlT[h * TT + tid];
            }
            g_lc[tid] = a; g_lml[tid] = c;
            float ha = 0.f, hb = 0.f;
            for (int nn = 0; nn < NMEN; nn++) {
                ha += (labels[nn * SQ + (SQ - 2)] == tid) ? 1.f : 0.f;
                hb += (labels[nn * SQ + (SQ - 1)] == tid) ? 1.f : 0.f;
            }
            g_histAlbl[tid] = ha; g_histBlbl[tid] = hb;
            g_histApred[tid] = 0.f; g_histBpred[tid] = 0.f;
        }
        if (tid >= TT && tid < TT + 8) g_red[tid - TT] = 0.f;
    }
}

// ============ K5: 3xTF32 logits GEMM + relu + outputs + hinge/CE/pred =====
#define XSTR 36
#define XS_TILE (128 * XSTR)
#define WS_TILE (40 * XSTR)

__global__ __launch_bounds__(128) void k5_logits(
    const float* __restrict__ X, const float* __restrict__ clsb,
    const int* __restrict__ labels, const int* __restrict__ padp,
    float* __restrict__ out)
{
    extern __shared__ float dyn[];
    float* Xs = dyn;                        // [2][128*36]
    float* Wh = dyn + 2 * XS_TILE;          // [2][40*36]
    float* Wl = Wh + 2 * WS_TILE;
    float* Gs = dyn;                        // reuse

    __shared__ float td_s[SQ];
    __shared__ float zc_s[TT], lc_s[TT], cb_s[TT];
    __shared__ float rh[4], rn[4], rv[4];

    const int n = blockIdx.x;
    const int tid = threadIdx.x;
    const int w = tid >> 5, lane = tid & 31;
    const int g = lane >> 2, tg = lane & 3;
    const int pad = padp[0];

    td_s[tid] = g_td[n * SQ + tid];
    if (tid < TT) {
        zc_s[tid] = g_zc[n * TT + tid];
        lc_s[tid] = g_lc[tid];
        cb_s[tid] = clsb[tid];
    }

    const float* Xbase = X + (size_t)n * SQ * HD;
    const uint32_t xs_u = (uint32_t)__cvta_generic_to_shared(Xs);
    const uint32_t wh_u = (uint32_t)__cvta_generic_to_shared(Wh);
    const uint32_t wl_u = (uint32_t)__cvta_generic_to_shared(Wl);

    #pragma unroll
    for (int f = 0; f < 8; f++)
        cp_async16(xs_u + (uint32_t)(tid * XSTR + f * 4) * 4,
                   Xbase + (size_t)tid * HD + f * 4);
    for (int idx = tid; idx < 320; idx += 128) {
        int r = idx >> 3, f = idx & 7;
        cp_async16(wh_u + (uint32_t)(r * XSTR + f * 4) * 4,
                   g_cwH + (size_t)r * HD + f * 4);
        cp_async16(wl_u + (uint32_t)(r * XSTR + f * 4) * 4,
                   g_cwL + (size_t)r * HD + f * 4);
    }
    CP_COMMIT();

    float acc[2][5][4];
    #pragma unroll
    for (int mt = 0; mt < 2; mt++)
        #pragma unroll
        for (int ni = 0; ni < 5; ni++)
            #pragma unroll
            for (int q = 0; q < 4; q++) acc[mt][ni][q] = 0.f;

    for (int kc = 0; kc < 24; kc++) {
        const int buf = kc & 1;
        if (kc + 1 < 24) {
            const int nb = (kc + 1) & 1;
            #pragma unroll
            for (int f = 0; f < 8; f++)
                cp_async16(xs_u + (uint32_t)(nb * XS_TILE + tid * XSTR + f * 4) * 4,
                           Xbase + (size_t)tid * HD + (kc + 1) * 32 + f * 4);
            for (int idx = tid; idx < 320; idx += 128) {
                int r = idx >> 3, f = idx & 7;
                cp_async16(wh_u + (uint32_t)(nb * WS_TILE + r * XSTR + f * 4) * 4,
                           g_cwH + (size_t)r * HD + (kc + 1) * 32 + f * 4);
                cp_async16(wl_u + (uint32_t)(nb * WS_TILE + r * XSTR + f * 4) * 4,
                           g_cwL + (size_t)r * HD + (kc + 1) * 32 + f * 4);
            }
            CP_COMMIT();
            CP_WAIT(1);
        } else {
            CP_WAIT(0);
        }
        __syncthreads();

        const float* Xb  = Xs + buf * XS_TILE;
        const float* Whb = Wh + buf * WS_TILE;
        const float* Wlb = Wl + buf * WS_TILE;
        #pragma unroll
        for (int ks = 0; ks < 4; ks++) {
            const int k8 = ks * 8;
            uint32_t ah[2][4], al[2][4];
            #pragma unroll
            for (int mt = 0; mt < 2; mt++) {
                int rb = w * 32 + mt * 16 + g;
                float x0 = Xb[rb * XSTR + k8 + tg];
                float x1 = Xb[(rb + 8) * XSTR + k8 + tg];
                float x2 = Xb[rb * XSTR + k8 + tg + 4];
                float x3 = Xb[(rb + 8) * XSTR + k8 + tg + 4];
                ah[mt][0] = cvt_tf32(x0);
                ah[mt][1] = cvt_tf32(x1);
                ah[mt][2] = cvt_tf32(x2);
                ah[mt][3] = cvt_tf32(x3);
                al[mt][0] = cvt_tf32(x0 - __uint_as_float(ah[mt][0]));
                al[mt][1] = cvt_tf32(x1 - __uint_as_float(ah[mt][1]));
                al[mt][2] = cvt_tf32(x2 - __uint_as_float(ah[mt][2]));
                al[mt][3] = cvt_tf32(x3 - __uint_as_float(ah[mt][3]));
            }
            #pragma unroll
            for (int ni = 0; ni < 5; ni++) {
                uint32_t bh0 = __float_as_uint(Whb[(ni * 8 + g) * XSTR + k8 + tg]);
                uint32_t bh1 = __float_as_uint(Whb[(ni * 8 + g) * XSTR + k8 + tg + 4]);
                uint32_t bl0 = __float_as_uint(Wlb[(ni * 8 + g) * XSTR + k8 + tg]);
                uint32_t bl1 = __float_as_uint(Wlb[(ni * 8 + g) * XSTR + k8 + tg + 4]);
                #pragma unroll
                for (int mt = 0; mt < 2; mt++) {
                    mma_tf32(acc[mt][ni], al[mt], bh0, bh1);
                    mma_tf32(acc[mt][ni], ah[mt], bl0, bl1);
                    mma_tf32(acc[mt][ni], ah[mt], bh0, bh1);
                }
            }
        }
        __syncthreads();
    }

    #pragma unroll
    for (int mt = 0; mt < 2; mt++)
        #pragma unroll
        for (int ni = 0; ni < 5; ni++)
            #pragma unroll
            for (int q = 0; q < 4; q++) {
                int r = w * 32 + mt * 16 + g + ((q >= 2) ? 8 : 0);
                int t = ni * 8 + tg * 2 + (q & 1);
                if (t < TT) {
                    float lg = fmaxf(acc[mt][ni][q] + td_s[r] * zc_s[t]
                                     + lc_s[t] + cb_s[t], 0.f);
                    Gs[r * 35 + t] = lg;
                    long gtok = (long)n * SQ + r;
                    out[LOGITS_OFF + (gtok + 1) * TT + t] = lg;
                    if (gtok == 0)        out[LOGITS_OFF + t] = lg;
                    if (gtok == NTOK - 1) out[LOGITS_OFF + (long)(NTOK + 1) * TT + t] = lg;
                }
            }
    __syncthreads();

    const int r = tid;
    const long gtok = (long)n * SQ + r;
    const int lbl = labels[gtok];
    const bool valid = (lbl != pad);
    const float* Lr = &Gs[r * 35];

    float mx = Lr[0]; int am = 0;
    #pragma unroll
    for (int t = 1; t < TT; t++) { float l = Lr[t]; if (l > mx) { mx = l; am = t; } }
    float se = 0.f;
    #pragma unroll
    for (int t = 0; t < TT; t++) se += __expf(Lr[t] - mx);
    float lse = mx + logf(se);
    float sy = Lr[lbl];
    float so = -1e30f;
    #pragma unroll
    for (int t = 0; t < TT; t++) if (t != lbl) so = fmaxf(so, Lr[t]);

    float hinge = valid ? fmaxf(0.f, 1.f + so - sy) : 0.f;
    float nll   = valid ? (lse - sy) : 0.f;
    float nv    = valid ? 1.f : 0.f;

    g_pred[gtok] = am;
    out[LBL_OFF + gtok + 1] = (float)lbl;
    if (gtok == 0)        out[LBL_OFF] = (float)lbl;
    if (gtok == NTOK - 1) out[LBL_OFF + NTOK + 1] = (float)lbl;

    if (r == SQ - 2) atomicAdd(&g_histApred[am], 1.f);
    if (r == SQ - 1) atomicAdd(&g_histBpred[am], 1.f);

    for (int o = 16; o > 0; o >>= 1) {
        hinge += __shfl_xor_sync(~0u, hinge, o);
        nll   += __shfl_xor_sync(~0u, nll, o);
        nv    += __shfl_xor_sync(~0u, nv, o);
    }
    if (lane == 0) { rh[w] = hinge; rn[w] = nll; rv[w] = nv; }
    __syncthreads();
    if (tid == 0) {
        float H = 0, N2 = 0, V = 0;
        for (int q = 0; q < 4; q++) { H += rh[q]; N2 += rn[q]; V += rv[q]; }
        atomicAdd(&g_red[0], H);
        atomicAdd(&g_red[1], N2);
        atomicAdd(&g_red[4], V);
    }
}

// ============ K6: energy local dots + ste (float4 vectorized) =============
__global__ __launch_bounds__(192) void k6_energy_ste(
    const float* __restrict__ X, const float* __restrict__ ml,
    const float* __restrict__ linb, const int* __restrict__ labels,
    const int* __restrict__ padp, float* __restrict__ out)
{
    __shared__ int lbl_s[SQ], pred_s[SQ];
    __shared__ float td_s[SQ];
    __shared__ float s_cnt, s_tdm, s_dL, s_dP;
    const int n = blockIdx.x, tid = threadIdx.x;
    const int lane = tid & 31;
    const int pad = padp[0];

    if (tid == 0) { s_cnt = 0.f; s_tdm = 0.f; s_dL = 0.f; s_dP = 0.f; }
    if (tid < SQ) {
        lbl_s[tid]  = labels[n * SQ + tid];
        pred_s[tid] = g_pred[n * SQ + tid];
        td_s[tid]   = g_td[n * SQ + tid];
    }
    __syncthreads();

    float cnt_p = 0.f, tdm_p = 0.f, dotL = 0.f, dotP = 0.f;
    if (tid < SQ) {
        int l = lbl_s[tid], p = pred_s[tid];
        float m = (p != pad) ? 1.f : 0.f;
        cnt_p = m; tdm_p = m * td_s[tid];
        dotL = td_s[tid] * g_zml[n * TT + l] + g_lml[l];
        dotP = td_s[tid] * g_zml[n * TT + p] + g_lml[p];
    }

    const int h0 = tid * 4;
    const float* Xn = X + (size_t)n * SQ * HD;
    float st0 = 0.f, st1 = 0.f, st2 = 0.f, st3 = 0.f;
    for (int s = 0; s < SQ; s++) {
        float4 x4 = *(const float4*)(Xn + (size_t)s * HD + h0);
        int l = lbl_s[s], p = pred_s[s];
        float4 mL = *(const float4*)(ml + (size_t)l * HD + h0);
        float4 mP = *(const float4*)(ml + (size_t)p * HD + h0);
        dotL += x4.x * mL.x + x4.y * mL.y + x4.z * mL.z + x4.w * mL.w;
        dotP += x4.x * mP.x + x4.y * mP.y + x4.z * mP.z + x4.w * mP.w;
        if (p != pad) { st0 += x4.x; st1 += x4.y; st2 += x4.z; st3 += x4.w; }
    }

    for (int o = 16; o > 0; o >>= 1) {
        cnt_p += __shfl_xor_sync(~0u, cnt_p, o);
        tdm_p += __shfl_xor_sync(~0u, tdm_p, o);
        dotL  += __shfl_xor_sync(~0u, dotL, o);
        dotP  += __shfl_xor_sync(~0u, dotP, o);
    }
    if (lane == 0) {
        atomicAdd(&s_cnt, cnt_p);
        atomicAdd(&s_tdm, tdm_p);
        atomicAdd(&s_dL, dotL);
        atomicAdd(&s_dP, dotP);
    }
    __syncthreads();
    if (tid == 0) {
        atomicAdd(&g_red[2], s_dL);
        atomicAdd(&g_red[3], s_dP);
    }

    const float cnt = s_cnt, tdm = s_tdm;
    float o0 = 0.f, o1 = 0.f, o2 = 0.f, o3 = 0.f;
    if (cnt > 0.f) {
        const float* zp = g_z + (size_t)n * HD + h0;
        const float* lp = linb + h0;
        float inv = 1.f / cnt;
        o0 = (st0 + tdm * zp[0] + cnt * lp[0]) * inv;
        o1 = (st1 + tdm * zp[1] + cnt * lp[1]) * inv;
        o2 = (st2 + tdm * zp[2] + cnt * lp[2]) * inv;
        o3 = (st3 + tdm * zp[3] + cnt * lp[3]) * inv;
    }
    float* op = out + STE_OFF + (size_t)n * HD + h0;
    op[0] = o0; op[1] = o1; op[2] = o2; op[3] = o3;
}

// ============ K7: finalize scalar loss =====================================
__global__ void k7_final(const float* __restrict__ mlab, float* __restrict__ out)
{
    __shared__ float s1[TT], s2[TT];
    int t = threadIdx.x;
    if (t < TT) {
        float rl = 0.f, rp = 0.f;
        for (int u = 0; u < TT; u++) {
            float mv = mlab[t * TT + u];
            rl += mv * g_histBlbl[u];
            rp += mv * g_histBpred[u];
        }
        s1[t] = g_histAlbl[t] * rl;
        s2[t] = g_histApred[t] * rp;
    }
    __syncthreads();
    if (t == 0) {
        float labL = 0.f, labP = 0.f;
        for (int u = 0; u < TT; u++) { labL += s1[u]; labP += s2[u]; }
        float nv = fmaxf(g_red[4], 1.f);
        float hinge = g_red[0] / nv;
        float ce = g_red[1] / nv;
        float El = g_red[2] + labL;
        float Ep = g_red[3] + labP;
        float lte = fmaxf(0.f, hinge + El - Ep);
        out[0] = 1.0f * lte + 0.5f * ce;
    }
}

extern "C" void kernel_launch(void* const* d_in, const int* in_sizes, int n_in,
                              void* d_out, int out_size)
{
    const float* X      = (const float*)d_in[0];
    const int*   labels = (const int*)  d_in[1];
    const int*   padp   = (const int*)  d_in[4];
    const float* Ww     = (const float*)d_in[6];
    const float* Wb     = (const float*)d_in[7];
    const float* vw     = (const float*)d_in[8];
    const float* clsw   = (const float*)d_in[10];
    const float* clsb   = (const float*)d_in[11];
    const float* ml     = (const float*)d_in[12];
    const float* mlab   = (const float*)d_in[13];
    const float* lw     = (const float*)d_in[14];
    const float* linb   = (const float*)d_in[15];
    float* out = (float*)d_out;
    (void)in_sizes; (void)n_in; (void)out_size;

    const int k1_smem = 4 * TILE_BF * 2;                       // 73728 bytes
    const int k5_smem = (2 * XS_TILE + 4 * WS_TILE) * 4;       // 48384 bytes
    cudaFuncSetAttribute(k1_mma, cudaFuncAttributeMaxDynamicSharedMemorySize, k1_smem);
    cudaFuncSetAttribute(k5_logits, cudaFuncAttributeMaxDynamicSharedMemorySize, k5_smem);

    c1_cvt<<<12288, 512>>>(X);
    c2_wt<<<dim3(24, 24), dim3(32, 8)>>>(Ww);
    c3_mlt<<<1, 1024>>>(ml);
    c4_cwt<<<120, 256>>>(clsw);
    k1_mma<<<dim3(NMEN, 3), 256, k1_smem>>>(Wb, vw);
    k2_softmax_head<<<NMEN, 192>>>();
    k3_z<<<dim3(64, 3), 256>>>(lw);
    k4_small<<<129, 272>>>(clsw, linb, labels);
    k5_logits<<<NMEN, 128, k5_smem>>>(X, clsb, labels, padp, out);
    k6_energy_ste<<<NMEN, 192>>>(X, ml, linb, labels, padp, out);
    k7_final<<<1, 64>>>(mlab, out);
}

// round 14
// speedup vs baseline: 1.1011x; 1.0931x over previous
#include <cuda_runtime.h>
#include <cuda_bf16.h>
#include <math.h>
#include <stdint.h>

#define NTOK  65536
#define NMEN  512
#define SQ    128
#define HD    768
#define TT    34

#define LOGITS_OFF 1
#define LBL_OFF    (1 + (NTOK + 2) * TT)
#define STE_OFF    (LBL_OFF + NTOK + 2)

// ---------------- scratch ----------------
__device__ __nv_bfloat16 g_xbf[(size_t)NTOK * HD];   // bf16 copy of X
__device__ __nv_bfloat16 g_wt[HD * HD];              // W transposed [j][k], bf16
__device__ float g_mlT[HD * TT];                     // mat_local transposed [h][t]
__device__ float g_cwH[40 * HD];                     // clsw^T hi (tf32)
__device__ float g_cwL[40 * HD];                     // clsw^T lo
__device__ float g_scoreP[12 * NTOK];                // partial scores per 64-col tile
__device__ float g_td[NTOK];
__device__ float g_head[NMEN * HD];
__device__ float g_z[NMEN * HD];
__device__ float g_zc[NMEN * TT];
__device__ float g_zml[NMEN * TT];
__device__ float g_lc[TT];
__device__ float g_lml[TT];
__device__ int   g_pred[NTOK];
__device__ float g_red[8];      // 0 hinge, 1 nll, 2 E_lbl_loc, 3 E_pred_loc, 4 n_valid
__device__ float g_histApred[TT], g_histBpred[TT];
__device__ float g_histAlbl[TT],  g_histBlbl[TT];

__device__ __forceinline__ float fast_tanh(float x) {
    float y; asm("tanh.approx.f32 %0, %1;" : "=f"(y) : "f"(x)); return y;
}

__device__ __forceinline__ void mma16816(float* c, const uint32_t* a,
                                         uint32_t b0, uint32_t b1) {
    asm volatile(
        "mma.sync.aligned.m16n8k16.row.col.f32.bf16.bf16.f32 "
        "{%0,%1,%2,%3}, {%4,%5,%6,%7}, {%8,%9}, {%0,%1,%2,%3};"
        : "+f"(c[0]), "+f"(c[1]), "+f"(c[2]), "+f"(c[3])
        : "r"(a[0]), "r"(a[1]), "r"(a[2]), "r"(a[3]), "r"(b0), "r"(b1));
}

__device__ __forceinline__ void mma_tf32(float* c, const uint32_t* a,
                                         uint32_t b0, uint32_t b1) {
    asm volatile(
        "mma.sync.aligned.m16n8k8.row.col.f32.tf32.tf32.f32 "
        "{%0,%1,%2,%3}, {%4,%5,%6,%7}, {%8,%9}, {%0,%1,%2,%3};"
        : "+f"(c[0]), "+f"(c[1]), "+f"(c[2]), "+f"(c[3])
        : "r"(a[0]), "r"(a[1]), "r"(a[2]), "r"(a[3]), "r"(b0), "r"(b1));
}

__device__ __forceinline__ void ldsm_x4(uint32_t& r0, uint32_t& r1,
                                        uint32_t& r2, uint32_t& r3, uint32_t addr) {
    asm volatile("ldmatrix.sync.aligned.m8n8.x4.shared.b16 {%0,%1,%2,%3}, [%4];"
                 : "=r"(r0), "=r"(r1), "=r"(r2), "=r"(r3) : "r"(addr));
}

__device__ __forceinline__ uint32_t cvt_tf32(float f) {
    uint32_t r; asm("cvt.rna.tf32.f32 %0, %1;" : "=r"(r) : "f"(f)); return r;
}

__device__ __forceinline__ void cp_async16(uint32_t dst, const void* src) {
    asm volatile("cp.async.ca.shared.global [%0], [%1], 16;"
                 :: "r"(dst), "l"(src));
}
#define CP_COMMIT() asm volatile("cp.async.commit_group;" ::: "memory")
#define CP_WAIT(n)  asm volatile("cp.async.wait_group %0;" :: "n"(n) : "memory")

// ============ C1: X fp32 -> bf16 ==========================================
__global__ __launch_bounds__(512) void c1_cvt(const float* __restrict__ X)
{
    size_t i = ((size_t)blockIdx.x * 512 + threadIdx.x) * 8;
    float4 a = *(const float4*)(X + i);
    float4 b = *(const float4*)(X + i + 4);
    __nv_bfloat162 h0 = __float22bfloat162_rn(make_float2(a.x, a.y));
    __nv_bfloat162 h1 = __float22bfloat162_rn(make_float2(a.z, a.w));
    __nv_bfloat162 h2 = __float22bfloat162_rn(make_float2(b.x, b.y));
    __nv_bfloat162 h3 = __float22bfloat162_rn(make_float2(b.z, b.w));
    uint4 o;
    o.x = *(uint32_t*)&h0; o.y = *(uint32_t*)&h1;
    o.z = *(uint32_t*)&h2; o.w = *(uint32_t*)&h3;
    *(uint4*)(g_xbf + i) = o;
}

// ============ C2: W transpose -> bf16 =====================================
__global__ void c2_wt(const float* __restrict__ W)
{
    __shared__ float t[32][33];
    int j0 = blockIdx.x * 32, k0 = blockIdx.y * 32;
    int tx = threadIdx.x, ty = threadIdx.y;
    #pragma unroll
    for (int q = 0; q < 32; q += 8)
        t[ty + q][tx] = W[(size_t)(k0 + ty + q) * HD + j0 + tx];
    __syncthreads();
    #pragma unroll
    for (int q = 0; q < 32; q += 8)
        g_wt[(size_t)(j0 + ty + q) * HD + k0 + tx] = __float2bfloat16(t[tx][ty + q]);
}

// ============ C3: mat_local transpose (parallel) ==========================
__global__ void c3_mlt(const float* __restrict__ ml)
{
    int i = blockIdx.x * 256 + threadIdx.x;
    if (i < HD * TT) {
        int h = i / TT, t = i - h * TT;
        g_mlT[i] = ml[(size_t)t * HD + h];
    }
}

// ============ C4: clsw transpose (+pad to 40 rows), tf32 hi/lo ============
__global__ void c4_cwt(const float* __restrict__ clsw)
{
    int i = blockIdx.x * 256 + threadIdx.x;
    if (i < 40 * HD) {
        int t = i / HD, k = i - t * HD;
        float v = (t < TT) ? clsw[(size_t)k * TT + t] : 0.f;
        uint32_t hi = cvt_tf32(v);
        g_cwH[i] = __uint_as_float(hi);
        g_cwL[i] = __uint_as_float(cvt_tf32(v - __uint_as_float(hi)));
    }
}

// ============ K1: HMMA partial score GEMM — 4x2 warp tile, 12 partials ====
// Warp (wm, wn): rows [wm*32,+32) x cols [jp*128 + wn*64, +64).
// Each warp owns complete 64-col row sums -> direct write, no CTA merge.
#define ASTR 72
#define TILE_BF (128 * ASTR)

__global__ __launch_bounds__(256, 2) void k1_mma(
    const float* __restrict__ Wb, const float* __restrict__ vw)
{
    extern __shared__ __nv_bfloat16 sm[];
    __nv_bfloat16* As = sm;
    __nv_bfloat16* Bs = sm + 2 * TILE_BF;

    const int tid = threadIdx.x;
    const int w = tid >> 5, lane = tid & 31;
    const int wm = w & 3, wn = w >> 2;
    const int g = lane >> 2, tg = lane & 3;
    const int n = blockIdx.x, jp = blockIdx.y;

    const __nv_bfloat16* Abase = g_xbf + (size_t)n * SQ * HD;
    const __nv_bfloat16* Bbase = g_wt + (size_t)jp * 128 * HD;

    const uint32_t as_u = (uint32_t)__cvta_generic_to_shared(As);
    const uint32_t bs_u = (uint32_t)__cvta_generic_to_shared(Bs);

    const int lr = tid >> 3, lf = tid & 7;

    #pragma unroll
    for (int q = 0; q < 4; q++) {
        int r = lr + q * 32;
        uint32_t off = (uint32_t)(r * ASTR + lf * 8) * 2;
        cp_async16(as_u + off, Abase + (size_t)r * HD + lf * 8);
        cp_async16(bs_u + off, Bbase + (size_t)r * HD + lf * 8);
    }
    CP_COMMIT();

    float c[2][8][4];
    #pragma unroll
    for (int mi = 0; mi < 2; mi++)
        #pragma unroll
        for (int ni = 0; ni < 8; ni++)
            #pragma unroll
            for (int q = 0; q < 4; q++) c[mi][ni][q] = 0.f;

    const uint32_t a_lrow = (uint32_t)(lane & 15);
    const uint32_t a_koff = (uint32_t)((lane >> 4) * 8);
    const uint32_t b_jrow = (uint32_t)(((lane >> 4) << 3) + (lane & 7));
    const uint32_t b_koff = (uint32_t)(((lane >> 3) & 1) * 8);

    for (int kc = 0; kc < 12; kc++) {
        const int buf = kc & 1;
        if (kc + 1 < 12) {
            const int nb = (kc + 1) & 1;
            #pragma unroll
            for (int q = 0; q < 4; q++) {
                int r = lr + q * 32;
                uint32_t off = (uint32_t)(nb * TILE_BF + r * ASTR + lf * 8) * 2;
                cp_async16(as_u + off, Abase + (size_t)r * HD + (kc + 1) * 64 + lf * 8);
                cp_async16(bs_u + off, Bbase + (size_t)r * HD + (kc + 1) * 64 + lf * 8);
            }
            CP_COMMIT();
            CP_WAIT(1);
        } else {
            CP_WAIT(0);
        }
        __syncthreads();

        const uint32_t ab_u = as_u + (uint32_t)(buf * TILE_BF) * 2;
        const uint32_t bb_u = bs_u + (uint32_t)(buf * TILE_BF) * 2;
        #pragma unroll
        for (int ks = 0; ks < 4; ks++) {
            uint32_t a[2][4];
            #pragma unroll
            for (int mi = 0; mi < 2; mi++)
                ldsm_x4(a[mi][0], a[mi][1], a[mi][2], a[mi][3],
                        ab_u + (uint32_t)((wm * 32 + mi * 16 + a_lrow) * ASTR
                                          + ks * 16 + a_koff) * 2);
            #pragma unroll
            for (int p = 0; p < 4; p++) {
                uint32_t b0, b1, b2, b3;
                ldsm_x4(b0, b1, b2, b3,
                        bb_u + (uint32_t)((wn * 64 + p * 16 + b_jrow) * ASTR
                                          + ks * 16 + b_koff) * 2);
                mma16816(c[0][2 * p],     a[0], b0, b1);
                mma16816(c[0][2 * p + 1], a[0], b2, b3);
                mma16816(c[1][2 * p],     a[1], b0, b1);
                mma16816(c[1][2 * p + 1], a[1], b2, b3);
            }
        }
        __syncthreads();
    }

    // epilogue: per-row partial score over this warp's 64 cols
    float s0 = 0.f, s1 = 0.f, s2 = 0.f, s3 = 0.f;
    #pragma unroll
    for (int ni = 0; ni < 8; ni++) {
        int j0 = jp * 128 + wn * 64 + ni * 8 + tg * 2;
        float w0 = __ldg(Wb + j0), w1 = __ldg(Wb + j0 + 1);
        float v0 = __ldg(vw + j0), v1 = __ldg(vw + j0 + 1);
        s0 += fast_tanh(c[0][ni][0] + w0) * v0 + fast_tanh(c[0][ni][1] + w1) * v1;
        s1 += fast_tanh(c[0][ni][2] + w0) * v0 + fast_tanh(c[0][ni][3] + w1) * v1;
        s2 += fast_tanh(c[1][ni][0] + w0) * v0 + fast_tanh(c[1][ni][1] + w1) * v1;
        s3 += fast_tanh(c[1][ni][2] + w0) * v0 + fast_tanh(c[1][ni][3] + w1) * v1;
    }
    #pragma unroll
    for (int o = 1; o <= 2; o <<= 1) {
        s0 += __shfl_xor_sync(~0u, s0, o);
        s1 += __shfl_xor_sync(~0u, s1, o);
        s2 += __shfl_xor_sync(~0u, s2, o);
        s3 += __shfl_xor_sync(~0u, s3, o);
    }
    if (tg == 0) {
        size_t base = (size_t)(jp * 2 + wn) * NTOK + n * SQ + wm * 32;
        g_scoreP[base + g]      = s0;
        g_scoreP[base + 8 + g]  = s1;
        g_scoreP[base + 16 + g] = s2;
        g_scoreP[base + 24 + g] = s3;
    }
}

// ============ K2: sum 12 partials + softmax + head (bf16 X) ================
__global__ __launch_bounds__(192) void k2_softmax_head()
{
    const int n = blockIdx.x;
    const int tid = threadIdx.x;
    const int lane = tid & 31, w = tid >> 5;
    __shared__ float sc[SQ];
    __shared__ float wr[8];

    float score = 0.f;
    if (tid < SQ) {
        #pragma unroll
        for (int p = 0; p < 12; p++)
            score += g_scoreP[(size_t)p * NTOK + n * SQ + tid];
    }
    if (tid < SQ) {
        float m = score;
        #pragma unroll
        for (int o = 16; o > 0; o >>= 1) m = fmaxf(m, __shfl_xor_sync(~0u, m, o));
        if (lane == 0) wr[w] = m;
    }
    __syncthreads();
    if (tid == 0) wr[4] = fmaxf(fmaxf(wr[0], wr[1]), fmaxf(wr[2], wr[3]));
    __syncthreads();
    float e = 0.f;
    if (tid < SQ) {
        e = __expf(score - wr[4]);
        float es = e;
        #pragma unroll
        for (int o = 16; o > 0; o >>= 1) es += __shfl_xor_sync(~0u, es, o);
        if (lane == 0) wr[w] = es;
    }
    __syncthreads();
    if (tid == 0) wr[5] = wr[0] + wr[1] + wr[2] + wr[3];
    __syncthreads();
    if (tid < SQ) {
        float td = e / wr[5];
        g_td[n * SQ + tid] = td;
        sc[tid] = td;
    }
    __syncthreads();

    const __nv_bfloat16* Xn = g_xbf + (size_t)n * SQ * HD;
    const int h0 = tid * 4;
    float a0 = 0.f, a1 = 0.f, a2 = 0.f, a3 = 0.f;
    #pragma unroll 4
    for (int s = 0; s < SQ; s++) {
        uint2 u = *(const uint2*)(Xn + (size_t)s * HD + h0);
        __nv_bfloat162 p0 = *(__nv_bfloat162*)&u.x;
        __nv_bfloat162 p1 = *(__nv_bfloat162*)&u.y;
        float t = sc[s];
        a0 += t * __bfloat162float(p0.x);
        a1 += t * __bfloat162float(p0.y);
        a2 += t * __bfloat162float(p1.x);
        a3 += t * __bfloat162float(p1.y);
    }
    float* hd = g_head + (size_t)n * HD + h0;
    hd[0] = a0; hd[1] = a1; hd[2] = a2; hd[3] = a3;
}

// ============ K3: z = head @ (lin_w[:H] + lin_w[H:]) =======================
__global__ __launch_bounds__(256) void k3_z(const float* __restrict__ lw)
{
    const int nb = blockIdx.x;
    const int cb = blockIdx.y;
    const int tid = threadIdx.x;
    __shared__ float hs[8 * HD];
    for (int i = tid; i < 8 * HD; i += 256)
        hs[i] = g_head[(size_t)nb * 8 * HD + i];
    __syncthreads();
    const int col = cb * 256 + tid;
    float acc[8] = {0, 0, 0, 0, 0, 0, 0, 0};
    for (int h = 0; h < HD; h++) {
        float w = lw[(size_t)h * HD + col] + lw[(size_t)(h + HD) * HD + col];
        #pragma unroll
        for (int q = 0; q < 8; q++) acc[q] += hs[q * HD + h] * w;
    }
    #pragma unroll
    for (int q = 0; q < 8; q++)
        g_z[(size_t)(nb * 8 + q) * HD + col] = acc[q];
}

// ============ K4: zc/zml (4 mentions/block); lc/lml/hists in last block ===
__global__ __launch_bounds__(272) void k4_small(
    const float* __restrict__ clsw, const float* __restrict__ linb,
    const int* __restrict__ labels)
{
    const int tid = threadIdx.x;
    if (blockIdx.x < 128) {
        __shared__ float zs[4 * HD];
        for (int i = tid; i < 4 * HD; i += 272)
            zs[i] = g_z[(size_t)blockIdx.x * 4 * HD + i];
        __syncthreads();
        const int g = tid / 68, t = tid - g * 68;
        const int b = blockIdx.x * 4 + g;
        const float* z = zs + g * HD;
        if (t < TT) {
            float a = 0.f;
            for (int h = 0; h < HD; h++) a += z[h] * clsw[h * TT + t];
            g_zc[b * TT + t] = a;
        } else {
            int tt = t - TT;
            float a = 0.f;
            for (int h = 0; h < HD; h++) a += z[h] * g_mlT[h * TT + tt];
            g_zml[b * TT + tt] = a;
        }
    } else {
        if (tid < TT) {
            float a = 0.f, c = 0.f;
            for (int h = 0; h < HD; h++) {
                float lb = linb[h];
                a += lb * clsw[h * TT + tid];
                c += lb * g_mlT[h * TT + tid];
            }
            g_lc[tid] = a; g_lml[tid] = c;
            float ha = 0.f, hb = 0.f;
            for (int nn = 0; nn < NMEN; nn++) {
                ha += (labels[nn * SQ + (SQ - 2)] == tid) ? 1.f : 0.f;
                hb += (labels[nn * SQ + (SQ - 1)] == tid) ? 1.f : 0.f;
            }
            g_histAlbl[tid] = ha; g_histBlbl[tid] = hb;
            g_histApred[tid] = 0.f; g_histBpred[tid] = 0.f;
        }
        if (tid >= TT && tid < TT + 8) g_red[tid - TT] = 0.f;
    }
}

// ============ K5: 3xTF32 logits GEMM + relu + outputs + hinge/CE/pred =====
#define XSTR 36
#define XS_TILE (128 * XSTR)
#define WS_TILE (40 * XSTR)

__global__ __launch_bounds__(128) void k5_logits(
    const float* __restrict__ X, const float* __restrict__ clsb,
    const int* __restrict__ labels, const int* __restrict__ padp,
    float* __restrict__ out)
{
    extern __shared__ float dyn[];
    float* Xs = dyn;                        // [2][128*36]
    float* Wh = dyn + 2 * XS_TILE;          // [2][40*36]
    float* Wl = Wh + 2 * WS_TILE;
    float* Gs = dyn;                        // reuse

    __shared__ float td_s[SQ];
    __shared__ float zc_s[TT], lc_s[TT], cb_s[TT];
    __shared__ float rh[4], rn[4], rv[4];

    const int n = blockIdx.x;
    const int tid = threadIdx.x;
    const int w = tid >> 5, lane = tid & 31;
    const int g = lane >> 2, tg = lane & 3;
    const int pad = padp[0];

    td_s[tid] = g_td[n * SQ + tid];
    if (tid < TT) {
        zc_s[tid] = g_zc[n * TT + tid];
        lc_s[tid] = g_lc[tid];
        cb_s[tid] = clsb[tid];
    }

    const float* Xbase = X + (size_t)n * SQ * HD;
    const uint32_t xs_u = (uint32_t)__cvta_generic_to_shared(Xs);
    const uint32_t wh_u = (uint32_t)__cvta_generic_to_shared(Wh);
    const uint32_t wl_u = (uint32_t)__cvta_generic_to_shared(Wl);

    #pragma unroll
    for (int f = 0; f < 8; f++)
        cp_async16(xs_u + (uint32_t)(tid * XSTR + f * 4) * 4,
                   Xbase + (size_t)tid * HD + f * 4);
    for (int idx = tid; idx < 320; idx += 128) {
        int r = idx >> 3, f = idx & 7;
        cp_async16(wh_u + (uint32_t)(r * XSTR + f * 4) * 4,
                   g_cwH + (size_t)r * HD + f * 4);
        cp_async16(wl_u + (uint32_t)(r * XSTR + f * 4) * 4,
                   g_cwL + (size_t)r * HD + f * 4);
    }
    CP_COMMIT();

    float acc[2][5][4];
    #pragma unroll
    for (int mt = 0; mt < 2; mt++)
        #pragma unroll
        for (int ni = 0; ni < 5; ni++)
            #pragma unroll
            for (int q = 0; q < 4; q++) acc[mt][ni][q] = 0.f;

    for (int kc = 0; kc < 24; kc++) {
        const int buf = kc & 1;
        if (kc + 1 < 24) {
            const int nb = (kc + 1) & 1;
            #pragma unroll
            for (int f = 0; f < 8; f++)
                cp_async16(xs_u + (uint32_t)(nb * XS_TILE + tid * XSTR + f * 4) * 4,
                           Xbase + (size_t)tid * HD + (kc + 1) * 32 + f * 4);
            for (int idx = tid; idx < 320; idx += 128) {
                int r = idx >> 3, f = idx & 7;
                cp_async16(wh_u + (uint32_t)(nb * WS_TILE + r * XSTR + f * 4) * 4,
                           g_cwH + (size_t)r * HD + (kc + 1) * 32 + f * 4);
                cp_async16(wl_u + (uint32_t)(nb * WS_TILE + r * XSTR + f * 4) * 4,
                           g_cwL + (size_t)r * HD + (kc + 1) * 32 + f * 4);
            }
            CP_COMMIT();
            CP_WAIT(1);
        } else {
            CP_WAIT(0);
        }
        __syncthreads();

        const float* Xb  = Xs + buf * XS_TILE;
        const float* Whb = Wh + buf * WS_TILE;
        const float* Wlb = Wl + buf * WS_TILE;
        #pragma unroll
        for (int ks = 0; ks < 4; ks++) {
            const int k8 = ks * 8;
            uint32_t ah[2][4], al[2][4];
            #pragma unroll
            for (int mt = 0; mt < 2; mt++) {
                int rb = w * 32 + mt * 16 + g;
                float x0 = Xb[rb * XSTR + k8 + tg];
                float x1 = Xb[(rb + 8) * XSTR + k8 + tg];
                float x2 = Xb[rb * XSTR + k8 + tg + 4];
                float x3 = Xb[(rb + 8) * XSTR + k8 + tg + 4];
                ah[mt][0] = cvt_tf32(x0);
                ah[mt][1] = cvt_tf32(x1);
                ah[mt][2] = cvt_tf32(x2);
                ah[mt][3] = cvt_tf32(x3);
                al[mt][0] = cvt_tf32(x0 - __uint_as_float(ah[mt][0]));
                al[mt][1] = cvt_tf32(x1 - __uint_as_float(ah[mt][1]));
                al[mt][2] = cvt_tf32(x2 - __uint_as_float(ah[mt][2]));
                al[mt][3] = cvt_tf32(x3 - __uint_as_float(ah[mt][3]));
            }
            #pragma unroll
            for (int ni = 0; ni < 5; ni++) {
                uint32_t bh0 = __float_as_uint(Whb[(ni * 8 + g) * XSTR + k8 + tg]);
                uint32_t bh1 = __float_as_uint(Whb[(ni * 8 + g) * XSTR + k8 + tg + 4]);
                uint32_t bl0 = __float_as_uint(Wlb[(ni * 8 + g) * XSTR + k8 + tg]);
                uint32_t bl1 = __float_as_uint(Wlb[(ni * 8 + g) * XSTR + k8 + tg + 4]);
                #pragma unroll
                for (int mt = 0; mt < 2; mt++) {
                    mma_tf32(acc[mt][ni], al[mt], bh0, bh1);
                    mma_tf32(acc[mt][ni], ah[mt], bl0, bl1);
                    mma_tf32(acc[mt][ni], ah[mt], bh0, bh1);
                }
            }
        }
        __syncthreads();
    }

    #pragma unroll
    for (int mt = 0; mt < 2; mt++)
        #pragma unroll
        for (int ni = 0; ni < 5; ni++)
            #pragma unroll
            for (int q = 0; q < 4; q++) {
                int r = w * 32 + mt * 16 + g + ((q >= 2) ? 8 : 0);
                int t = ni * 8 + tg * 2 + (q & 1);
                if (t < TT) {
                    float lg = fmaxf(acc[mt][ni][q] + td_s[r] * zc_s[t]
                                     + lc_s[t] + cb_s[t], 0.f);
                    Gs[r * 35 + t] = lg;
                    long gtok = (long)n * SQ + r;
                    out[LOGITS_OFF + (gtok + 1) * TT + t] = lg;
                    if (gtok == 0)        out[LOGITS_OFF + t] = lg;
                    if (gtok == NTOK - 1) out[LOGITS_OFF + (long)(NTOK + 1) * TT + t] = lg;
                }
            }
    __syncthreads();

    const int r = tid;
    const long gtok = (long)n * SQ + r;
    const int lbl = labels[gtok];
    const bool valid = (lbl != pad);
    const float* Lr = &Gs[r * 35];

    float mx = Lr[0]; int am = 0;
    #pragma unroll
    for (int t = 1; t < TT; t++) { float l = Lr[t]; if (l > mx) { mx = l; am = t; } }
    float se = 0.f;
    #pragma unroll
    for (int t = 0; t < TT; t++) se += __expf(Lr[t] - mx);
    float lse = mx + logf(se);
    float sy = Lr[lbl];
    float so = -1e30f;
    #pragma unroll
    for (int t = 0; t < TT; t++) if (t != lbl) so = fmaxf(so, Lr[t]);

    float hinge = valid ? fmaxf(0.f, 1.f + so - sy) : 0.f;
    float nll   = valid ? (lse - sy) : 0.f;
    float nv    = valid ? 1.f : 0.f;

    g_pred[gtok] = am;
    out[LBL_OFF + gtok + 1] = (float)lbl;
    if (gtok == 0)        out[LBL_OFF] = (float)lbl;
    if (gtok == NTOK - 1) out[LBL_OFF + NTOK + 1] = (float)lbl;

    if (r == SQ - 2) atomicAdd(&g_histApred[am], 1.f);
    if (r == SQ - 1) atomicAdd(&g_histBpred[am], 1.f);

    for (int o = 16; o > 0; o >>= 1) {
        hinge += __shfl_xor_sync(~0u, hinge, o);
        nll   += __shfl_xor_sync(~0u, nll, o);
        nv    += __shfl_xor_sync(~0u, nv, o);
    }
    if (lane == 0) { rh[w] = hinge; rn[w] = nll; rv[w] = nv; }
    __syncthreads();
    if (tid == 0) {
        float H = 0, N2 = 0, V = 0;
        for (int q = 0; q < 4; q++) { H += rh[q]; N2 += rn[q]; V += rv[q]; }
        atomicAdd(&g_red[0], H);
        atomicAdd(&g_red[1], N2);
        atomicAdd(&g_red[4], V);
    }
}

// ============ K6: energy local dots + ste (float4 vectorized) =============
__global__ __launch_bounds__(192) void k6_energy_ste(
    const float* __restrict__ X, const float* __restrict__ ml,
    const float* __restrict__ linb, const int* __restrict__ labels,
    const int* __restrict__ padp, float* __restrict__ out)
{
    __shared__ int lbl_s[SQ], pred_s[SQ];
    __shared__ float td_s[SQ];
    __shared__ float s_cnt, s_tdm, s_dL, s_dP;
    const int n = blockIdx.x, tid = threadIdx.x;
    const int lane = tid & 31;
    const int pad = padp[0];

    if (tid == 0) { s_cnt = 0.f; s_tdm = 0.f; s_dL = 0.f; s_dP = 0.f; }
    if (tid < SQ) {
        lbl_s[tid]  = labels[n * SQ + tid];
        pred_s[tid] = g_pred[n * SQ + tid];
        td_s[tid]   = g_td[n * SQ + tid];
    }
    __syncthreads();

    float cnt_p = 0.f, tdm_p = 0.f, dotL = 0.f, dotP = 0.f;
    if (tid < SQ) {
        int l = lbl_s[tid], p = pred_s[tid];
        float m = (p != pad) ? 1.f : 0.f;
        cnt_p = m; tdm_p = m * td_s[tid];
        dotL = td_s[tid] * g_zml[n * TT + l] + g_lml[l];
        dotP = td_s[tid] * g_zml[n * TT + p] + g_lml[p];
    }

    const int h0 = tid * 4;
    const float* Xn = X + (size_t)n * SQ * HD;
    float st0 = 0.f, st1 = 0.f, st2 = 0.f, st3 = 0.f;
    for (int s = 0; s < SQ; s++) {
        float4 x4 = *(const float4*)(Xn + (size_t)s * HD + h0);
        int l = lbl_s[s], p = pred_s[s];
        float4 mL = *(const float4*)(ml + (size_t)l * HD + h0);
        float4 mP = *(const float4*)(ml + (size_t)p * HD + h0);
        dotL += x4.x * mL.x + x4.y * mL.y + x4.z * mL.z + x4.w * mL.w;
        dotP += x4.x * mP.x + x4.y * mP.y + x4.z * mP.z + x4.w * mP.w;
        if (p != pad) { st0 += x4.x; st1 += x4.y; st2 += x4.z; st3 += x4.w; }
    }

    for (int o = 16; o > 0; o >>= 1) {
        cnt_p += __shfl_xor_sync(~0u, cnt_p, o);
        tdm_p += __shfl_xor_sync(~0u, tdm_p, o);
        dotL  += __shfl_xor_sync(~0u, dotL, o);
        dotP  += __shfl_xor_sync(~0u, dotP, o);
    }
    if (lane == 0) {
        atomicAdd(&s_cnt, cnt_p);
        atomicAdd(&s_tdm, tdm_p);
        atomicAdd(&s_dL, dotL);
        atomicAdd(&s_dP, dotP);
    }
    __syncthreads();
    if (tid == 0) {
        atomicAdd(&g_red[2], s_dL);
        atomicAdd(&g_red[3], s_dP);
    }

    const float cnt = s_cnt, tdm = s_tdm;
    float o0 = 0.f, o1 = 0.f, o2 = 0.f, o3 = 0.f;
    if (cnt > 0.f) {
        const float* zp = g_z + (size_t)n * HD + h0;
        const float* lp = linb + h0;
        float inv = 1.f / cnt;
        o0 = (st0 + tdm * zp[0] + cnt * lp[0]) * inv;
        o1 = (st1 + tdm * zp[1] + cnt * lp[1]) * inv;
        o2 = (st2 + tdm * zp[2] + cnt * lp[2]) * inv;
        o3 = (st3 + tdm * zp[3] + cnt * lp[3]) * inv;
    }
    float* op = out + STE_OFF + (size_t)n * HD + h0;
    op[0] = o0; op[1] = o1; op[2] = o2; op[3] = o3;
}

// ============ K7: finalize scalar loss =====================================
__global__ void k7_final(const float* __restrict__ mlab, float* __restrict__ out)
{
    __shared__ float s1[TT], s2[TT];
    int t = threadIdx.x;
    if (t < TT) {
        float rl = 0.f, rp = 0.f;
        for (int u = 0; u < TT; u++) {
            float mv = mlab[t * TT + u];
            rl += mv * g_histBlbl[u];
            rp += mv * g_histBpred[u];
        }
        s1[t] = g_histAlbl[t] * rl;
        s2[t] = g_histApred[t] * rp;
    }
    __syncthreads();
    if (t == 0) {
        float labL = 0.f, labP = 0.f;
        for (int u = 0; u < TT; u++) { labL += s1[u]; labP += s2[u]; }
        float nv = fmaxf(g_red[4], 1.f);
        float hinge = g_red[0] / nv;
        float ce = g_red[1] / nv;
        float El = g_red[2] + labL;
        float Ep = g_red[3] + labP;
        float lte = fmaxf(0.f, hinge + El - Ep);
        out[0] = 1.0f * lte + 0.5f * ce;
    }
}

extern "C" void kernel_launch(void* const* d_in, const int* in_sizes, int n_in,
                              void* d_out, int out_size)
{
    const float* X      = (const float*)d_in[0];
    const int*   labels = (const int*)  d_in[1];
    const int*   padp   = (const int*)  d_in[4];
    const float* Ww     = (const float*)d_in[6];
    const float* Wb     = (const float*)d_in[7];
    const float* vw     = (const float*)d_in[8];
    const float* clsw   = (const float*)d_in[10];
    const float* clsb   = (const float*)d_in[11];
    const float* ml     = (const float*)d_in[12];
    const float* mlab   = (const float*)d_in[13];
    const float* lw     = (const float*)d_in[14];
    const float* linb   = (const float*)d_in[15];
    float* out = (float*)d_out;
    (void)in_sizes; (void)n_in; (void)out_size;

    const int k1_smem = 4 * TILE_BF * 2;                       // 73728 bytes
    const int k5_smem = (2 * XS_TILE + 4 * WS_TILE) * 4;       // 48384 bytes
    cudaFuncSetAttribute(k1_mma, cudaFuncAttributeMaxDynamicSharedMemorySize, k1_smem);
    cudaFuncSetAttribute(k5_logits, cudaFuncAttributeMaxDynamicSharedMemorySize, k5_smem);

    c1_cvt<<<12288, 512>>>(X);
    c2_wt<<<dim3(24, 24), dim3(32, 8)>>>(Ww);
    c3_mlt<<<102, 256>>>(ml);
    c4_cwt<<<120, 256>>>(clsw);
    k1_mma<<<dim3(NMEN, 6), 256, k1_smem>>>(Wb, vw);
    k2_softmax_head<<<NMEN, 192>>>();
    k3_z<<<dim3(64, 3), 256>>>(lw);
    k4_small<<<129, 272>>>(clsw, linb, labels);
    k5_logits<<<NMEN, 128, k5_smem>>>(X, clsb, labels, padp, out);
    k6_energy_ste<<<NMEN, 192>>>(X, ml, linb, labels, padp, out);
    k7_final<<<1, 64>>>(mlab, out);
}

// round 15
// speedup vs baseline: 1.1377x; 1.0332x over previous
#include <cuda_runtime.h>
#include <cuda_bf16.h>
#include <math.h>
#include <stdint.h>

#define NTOK  65536
#define NMEN  512
#define SQ    128
#define HD    768
#define TT    34

#define LOGITS_OFF 1
#define LBL_OFF    (1 + (NTOK + 2) * TT)
#define STE_OFF    (LBL_OFF + NTOK + 2)

// ---------------- scratch ----------------
__device__ __nv_bfloat16 g_xbf[(size_t)NTOK * HD];   // bf16 copy of X
__device__ __nv_bfloat16 g_wt[HD * HD];              // W transposed [j][k], bf16
__device__ float g_mlT[HD * TT];                     // mat_local transposed [h][t]
__device__ float g_cwH[40 * HD];                     // clsw^T hi (tf32)
__device__ float g_cwL[40 * HD];                     // clsw^T lo
__device__ float g_scoreP[12 * NTOK];                // partial scores per 64-col tile
__device__ float g_td[NTOK];
__device__ float g_head[NMEN * HD];
__device__ float g_z[NMEN * HD];
__device__ float g_zc[NMEN * TT];
__device__ float g_zml[NMEN * TT];
__device__ float g_lc[TT];
__device__ float g_lml[TT];
__device__ int   g_pred[NTOK];
__device__ float g_red[8];      // 0 hinge, 1 nll, 2 E_lbl_loc, 3 E_pred_loc, 4 n_valid
__device__ float g_histApred[TT], g_histBpred[TT];
__device__ float g_histAlbl[TT],  g_histBlbl[TT];

__device__ __forceinline__ float fast_tanh(float x) {
    float y; asm("tanh.approx.f32 %0, %1;" : "=f"(y) : "f"(x)); return y;
}

__device__ __forceinline__ void mma16816(float* c, const uint32_t* a,
                                         uint32_t b0, uint32_t b1) {
    asm volatile(
        "mma.sync.aligned.m16n8k16.row.col.f32.bf16.bf16.f32 "
        "{%0,%1,%2,%3}, {%4,%5,%6,%7}, {%8,%9}, {%0,%1,%2,%3};"
        : "+f"(c[0]), "+f"(c[1]), "+f"(c[2]), "+f"(c[3])
        : "r"(a[0]), "r"(a[1]), "r"(a[2]), "r"(a[3]), "r"(b0), "r"(b1));
}

__device__ __forceinline__ void mma_tf32(float* c, const uint32_t* a,
                                         uint32_t b0, uint32_t b1) {
    asm volatile(
        "mma.sync.aligned.m16n8k8.row.col.f32.tf32.tf32.f32 "
        "{%0,%1,%2,%3}, {%4,%5,%6,%7}, {%8,%9}, {%0,%1,%2,%3};"
        : "+f"(c[0]), "+f"(c[1]), "+f"(c[2]), "+f"(c[3])
        : "r"(a[0]), "r"(a[1]), "r"(a[2]), "r"(a[3]), "r"(b0), "r"(b1));
}

__device__ __forceinline__ void ldsm_x4(uint32_t& r0, uint32_t& r1,
                                        uint32_t& r2, uint32_t& r3, uint32_t addr) {
    asm volatile("ldmatrix.sync.aligned.m8n8.x4.shared.b16 {%0,%1,%2,%3}, [%4];"
                 : "=r"(r0), "=r"(r1), "=r"(r2), "=r"(r3) : "r"(addr));
}

__device__ __forceinline__ uint32_t cvt_tf32(float f) {
    uint32_t r; asm("cvt.rna.tf32.f32 %0, %1;" : "=r"(r) : "f"(f)); return r;
}

__device__ __forceinline__ void cp_async16(uint32_t dst, const void* src) {
    asm volatile("cp.async.ca.shared.global [%0], [%1], 16;"
                 :: "r"(dst), "l"(src));
}
#define CP_COMMIT() asm volatile("cp.async.commit_group;" ::: "memory")
#define CP_WAIT(n)  asm volatile("cp.async.wait_group %0;" :: "n"(n) : "memory")

// ============ C1: X fp32 -> bf16 ==========================================
__global__ __launch_bounds__(512) void c1_cvt(const float* __restrict__ X)
{
    size_t i = ((size_t)blockIdx.x * 512 + threadIdx.x) * 8;
    float4 a = *(const float4*)(X + i);
    float4 b = *(const float4*)(X + i + 4);
    __nv_bfloat162 h0 = __float22bfloat162_rn(make_float2(a.x, a.y));
    __nv_bfloat162 h1 = __float22bfloat162_rn(make_float2(a.z, a.w));
    __nv_bfloat162 h2 = __float22bfloat162_rn(make_float2(b.x, b.y));
    __nv_bfloat162 h3 = __float22bfloat162_rn(make_float2(b.z, b.w));
    uint4 o;
    o.x = *(uint32_t*)&h0; o.y = *(uint32_t*)&h1;
    o.z = *(uint32_t*)&h2; o.w = *(uint32_t*)&h3;
    *(uint4*)(g_xbf + i) = o;
}

// ============ C2: W transpose -> bf16 =====================================
__global__ void c2_wt(const float* __restrict__ W)
{
    __shared__ float t[32][33];
    int j0 = blockIdx.x * 32, k0 = blockIdx.y * 32;
    int tx = threadIdx.x, ty = threadIdx.y;
    #pragma unroll
    for (int q = 0; q < 32; q += 8)
        t[ty + q][tx] = W[(size_t)(k0 + ty + q) * HD + j0 + tx];
    __syncthreads();
    #pragma unroll
    for (int q = 0; q < 32; q += 8)
        g_wt[(size_t)(j0 + ty + q) * HD + k0 + tx] = __float2bfloat16(t[tx][ty + q]);
}

// ============ C3: mat_local transpose (parallel) ==========================
__global__ void c3_mlt(const float* __restrict__ ml)
{
    int i = blockIdx.x * 256 + threadIdx.x;
    if (i < HD * TT) {
        int h = i / TT, t = i - h * TT;
        g_mlT[i] = ml[(size_t)t * HD + h];
    }
}

// ============ C4: clsw transpose (+pad to 40 rows), tf32 hi/lo ============
__global__ void c4_cwt(const float* __restrict__ clsw)
{
    int i = blockIdx.x * 256 + threadIdx.x;
    if (i < 40 * HD) {
        int t = i / HD, k = i - t * HD;
        float v = (t < TT) ? clsw[(size_t)k * TT + t] : 0.f;
        uint32_t hi = cvt_tf32(v);
        g_cwH[i] = __uint_as_float(hi);
        g_cwL[i] = __uint_as_float(cvt_tf32(v - __uint_as_float(hi)));
    }
}

// ============ K1: HMMA partial score GEMM — 4x2 warp tile, 12 partials ====
#define ASTR 72
#define TILE_BF (128 * ASTR)

__global__ __launch_bounds__(256, 2) void k1_mma(
    const float* __restrict__ Wb, const float* __restrict__ vw)
{
    extern __shared__ __nv_bfloat16 sm[];
    __nv_bfloat16* As = sm;
    __nv_bfloat16* Bs = sm + 2 * TILE_BF;

    const int tid = threadIdx.x;
    const int w = tid >> 5, lane = tid & 31;
    const int wm = w & 3, wn = w >> 2;
    const int g = lane >> 2, tg = lane & 3;
    const int n = blockIdx.x, jp = blockIdx.y;

    const __nv_bfloat16* Abase = g_xbf + (size_t)n * SQ * HD;
    const __nv_bfloat16* Bbase = g_wt + (size_t)jp * 128 * HD;

    const uint32_t as_u = (uint32_t)__cvta_generic_to_shared(As);
    const uint32_t bs_u = (uint32_t)__cvta_generic_to_shared(Bs);

    const int lr = tid >> 3, lf = tid & 7;

    #pragma unroll
    for (int q = 0; q < 4; q++) {
        int r = lr + q * 32;
        uint32_t off = (uint32_t)(r * ASTR + lf * 8) * 2;
        cp_async16(as_u + off, Abase + (size_t)r * HD + lf * 8);
        cp_async16(bs_u + off, Bbase + (size_t)r * HD + lf * 8);
    }
    CP_COMMIT();

    float c[2][8][4];
    #pragma unroll
    for (int mi = 0; mi < 2; mi++)
        #pragma unroll
        for (int ni = 0; ni < 8; ni++)
            #pragma unroll
            for (int q = 0; q < 4; q++) c[mi][ni][q] = 0.f;

    const uint32_t a_lrow = (uint32_t)(lane & 15);
    const uint32_t a_koff = (uint32_t)((lane >> 4) * 8);
    const uint32_t b_jrow = (uint32_t)(((lane >> 4) << 3) + (lane & 7));
    const uint32_t b_koff = (uint32_t)(((lane >> 3) & 1) * 8);

    for (int kc = 0; kc < 12; kc++) {
        const int buf = kc & 1;
        if (kc + 1 < 12) {
            const int nb = (kc + 1) & 1;
            #pragma unroll
            for (int q = 0; q < 4; q++) {
                int r = lr + q * 32;
                uint32_t off = (uint32_t)(nb * TILE_BF + r * ASTR + lf * 8) * 2;
                cp_async16(as_u + off, Abase + (size_t)r * HD + (kc + 1) * 64 + lf * 8);
                cp_async16(bs_u + off, Bbase + (size_t)r * HD + (kc + 1) * 64 + lf * 8);
            }
            CP_COMMIT();
            CP_WAIT(1);
        } else {
            CP_WAIT(0);
        }
        __syncthreads();

        const uint32_t ab_u = as_u + (uint32_t)(buf * TILE_BF) * 2;
        const uint32_t bb_u = bs_u + (uint32_t)(buf * TILE_BF) * 2;
        #pragma unroll
        for (int ks = 0; ks < 4; ks++) {
            uint32_t a[2][4];
            #pragma unroll
            for (int mi = 0; mi < 2; mi++)
                ldsm_x4(a[mi][0], a[mi][1], a[mi][2], a[mi][3],
                        ab_u + (uint32_t)((wm * 32 + mi * 16 + a_lrow) * ASTR
                                          + ks * 16 + a_koff) * 2);
            #pragma unroll
            for (int p = 0; p < 4; p++) {
                uint32_t b0, b1, b2, b3;
                ldsm_x4(b0, b1, b2, b3,
                        bb_u + (uint32_t)((wn * 64 + p * 16 + b_jrow) * ASTR
                                          + ks * 16 + b_koff) * 2);
                mma16816(c[0][2 * p],     a[0], b0, b1);
                mma16816(c[0][2 * p + 1], a[0], b2, b3);
                mma16816(c[1][2 * p],     a[1], b0, b1);
                mma16816(c[1][2 * p + 1], a[1], b2, b3);
            }
        }
        __syncthreads();
    }

    float s0 = 0.f, s1 = 0.f, s2 = 0.f, s3 = 0.f;
    #pragma unroll
    for (int ni = 0; ni < 8; ni++) {
        int j0 = jp * 128 + wn * 64 + ni * 8 + tg * 2;
        float w0 = __ldg(Wb + j0), w1 = __ldg(Wb + j0 + 1);
        float v0 = __ldg(vw + j0), v1 = __ldg(vw + j0 + 1);
        s0 += fast_tanh(c[0][ni][0] + w0) * v0 + fast_tanh(c[0][ni][1] + w1) * v1;
        s1 += fast_tanh(c[0][ni][2] + w0) * v0 + fast_tanh(c[0][ni][3] + w1) * v1;
        s2 += fast_tanh(c[1][ni][0] + w0) * v0 + fast_tanh(c[1][ni][1] + w1) * v1;
        s3 += fast_tanh(c[1][ni][2] + w0) * v0 + fast_tanh(c[1][ni][3] + w1) * v1;
    }
    #pragma unroll
    for (int o = 1; o <= 2; o <<= 1) {
        s0 += __shfl_xor_sync(~0u, s0, o);
        s1 += __shfl_xor_sync(~0u, s1, o);
        s2 += __shfl_xor_sync(~0u, s2, o);
        s3 += __shfl_xor_sync(~0u, s3, o);
    }
    if (tg == 0) {
        size_t base = (size_t)(jp * 2 + wn) * NTOK + n * SQ + wm * 32;
        g_scoreP[base + g]      = s0;
        g_scoreP[base + 8 + g]  = s1;
        g_scoreP[base + 16 + g] = s2;
        g_scoreP[base + 24 + g] = s3;
    }
}

// ============ K2: sum 12 partials + softmax + head (bf16 X) ================
__global__ __launch_bounds__(192) void k2_softmax_head()
{
    const int n = blockIdx.x;
    const int tid = threadIdx.x;
    const int lane = tid & 31, w = tid >> 5;
    __shared__ float sc[SQ];
    __shared__ float wr[8];

    float score = 0.f;
    if (tid < SQ) {
        #pragma unroll
        for (int p = 0; p < 12; p++)
            score += g_scoreP[(size_t)p * NTOK + n * SQ + tid];
    }
    if (tid < SQ) {
        float m = score;
        #pragma unroll
        for (int o = 16; o > 0; o >>= 1) m = fmaxf(m, __shfl_xor_sync(~0u, m, o));
        if (lane == 0) wr[w] = m;
    }
    __syncthreads();
    if (tid == 0) wr[4] = fmaxf(fmaxf(wr[0], wr[1]), fmaxf(wr[2], wr[3]));
    __syncthreads();
    float e = 0.f;
    if (tid < SQ) {
        e = __expf(score - wr[4]);
        float es = e;
        #pragma unroll
        for (int o = 16; o > 0; o >>= 1) es += __shfl_xor_sync(~0u, es, o);
        if (lane == 0) wr[w] = es;
    }
    __syncthreads();
    if (tid == 0) wr[5] = wr[0] + wr[1] + wr[2] + wr[3];
    __syncthreads();
    if (tid < SQ) {
        float td = e / wr[5];
        g_td[n * SQ + tid] = td;
        sc[tid] = td;
    }
    __syncthreads();

    const __nv_bfloat16* Xn = g_xbf + (size_t)n * SQ * HD;
    const int h0 = tid * 4;
    float a0 = 0.f, a1 = 0.f, a2 = 0.f, a3 = 0.f;
    #pragma unroll 4
    for (int s = 0; s < SQ; s++) {
        uint2 u = *(const uint2*)(Xn + (size_t)s * HD + h0);
        __nv_bfloat162 p0 = *(__nv_bfloat162*)&u.x;
        __nv_bfloat162 p1 = *(__nv_bfloat162*)&u.y;
        float t = sc[s];
        a0 += t * __bfloat162float(p0.x);
        a1 += t * __bfloat162float(p0.y);
        a2 += t * __bfloat162float(p1.x);
        a3 += t * __bfloat162float(p1.y);
    }
    float* hd = g_head + (size_t)n * HD + h0;
    hd[0] = a0; hd[1] = a1; hd[2] = a2; hd[3] = a3;
}

// ============ K3: z = head @ (lin_w[:H] + lin_w[H:]) =======================
__global__ __launch_bounds__(256) void k3_z(const float* __restrict__ lw)
{
    const int nb = blockIdx.x;
    const int cb = blockIdx.y;
    const int tid = threadIdx.x;
    __shared__ float hs[8 * HD];
    for (int i = tid; i < 8 * HD; i += 256)
        hs[i] = g_head[(size_t)nb * 8 * HD + i];
    __syncthreads();
    const int col = cb * 256 + tid;
    float acc[8] = {0, 0, 0, 0, 0, 0, 0, 0};
    for (int h = 0; h < HD; h++) {
        float w = lw[(size_t)h * HD + col] + lw[(size_t)(h + HD) * HD + col];
        #pragma unroll
        for (int q = 0; q < 8; q++) acc[q] += hs[q * HD + h] * w;
    }
    #pragma unroll
    for (int q = 0; q < 8; q++)
        g_z[(size_t)(nb * 8 + q) * HD + col] = acc[q];
}

// ============ K4: zc/zml (4 mentions/block); lc/lml/hists in last block ===
__global__ __launch_bounds__(272) void k4_small(
    const float* __restrict__ clsw, const float* __restrict__ linb,
    const int* __restrict__ labels)
{
    const int tid = threadIdx.x;
    if (blockIdx.x < 128) {
        __shared__ float zs[4 * HD];
        for (int i = tid; i < 4 * HD; i += 272)
            zs[i] = g_z[(size_t)blockIdx.x * 4 * HD + i];
        __syncthreads();
        const int g = tid / 68, t = tid - g * 68;
        const int b = blockIdx.x * 4 + g;
        const float* z = zs + g * HD;
        if (t < TT) {
            float a = 0.f;
            for (int h = 0; h < HD; h++) a += z[h] * clsw[h * TT + t];
            g_zc[b * TT + t] = a;
        } else {
            int tt = t - TT;
            float a = 0.f;
            for (int h = 0; h < HD; h++) a += z[h] * g_mlT[h * TT + tt];
            g_zml[b * TT + tt] = a;
        }
    } else {
        if (tid < TT) {
            float a = 0.f, c = 0.f;
            for (int h = 0; h < HD; h++) {
                float lb = linb[h];
                a += lb * clsw[h * TT + tid];
                c += lb * g_mlT[h * TT + tid];
            }
            g_lc[tid] = a; g_lml[tid] = c;
            float ha = 0.f, hb = 0.f;
            for (int nn = 0; nn < NMEN; nn++) {
                ha += (labels[nn * SQ + (SQ - 2)] == tid) ? 1.f : 0.f;
                hb += (labels[nn * SQ + (SQ - 1)] == tid) ? 1.f : 0.f;
            }
            g_histAlbl[tid] = ha; g_histBlbl[tid] = hb;
            g_histApred[tid] = 0.f; g_histBpred[tid] = 0.f;
        }
        if (tid >= TT && tid < TT + 8) g_red[tid - TT] = 0.f;
    }
}

// ============ K5: 3xTF32 logits GEMM — 256 threads / 8 warps ==============
// Warp w: rows [w*16, w*16+16). 20 acc regs/thread.
#define XSTR 36
#define XS_TILE (128 * XSTR)
#define WS_TILE (40 * XSTR)

__global__ __launch_bounds__(256) void k5_logits(
    const float* __restrict__ X, const float* __restrict__ clsb,
    const int* __restrict__ labels, const int* __restrict__ padp,
    float* __restrict__ out)
{
    extern __shared__ float dyn[];
    float* Xs = dyn;                        // [2][128*36]
    float* Wh = dyn + 2 * XS_TILE;          // [2][40*36]
    float* Wl = Wh + 2 * WS_TILE;
    float* Gs = dyn;                        // reuse

    __shared__ float td_s[SQ];
    __shared__ float zc_s[TT], lc_s[TT], cb_s[TT];
    __shared__ float rh[4], rn[4], rv[4];

    const int n = blockIdx.x;
    const int tid = threadIdx.x;
    const int w = tid >> 5, lane = tid & 31;
    const int g = lane >> 2, tg = lane & 3;
    const int pad = padp[0];

    if (tid < SQ) td_s[tid] = g_td[n * SQ + tid];
    if (tid >= SQ && tid < SQ + TT) {
        int t = tid - SQ;
        zc_s[t] = g_zc[n * TT + t];
        lc_s[t] = g_lc[t];
        cb_s[t] = clsb[t];
    }

    const float* Xbase = X + (size_t)n * SQ * HD;
    const uint32_t xs_u = (uint32_t)__cvta_generic_to_shared(Xs);
    const uint32_t wh_u = (uint32_t)__cvta_generic_to_shared(Wh);
    const uint32_t wl_u = (uint32_t)__cvta_generic_to_shared(Wl);

    const int xrow = tid >> 1, xcol = (tid & 1) * 16;
    #pragma unroll
    for (int f = 0; f < 4; f++)
        cp_async16(xs_u + (uint32_t)(xrow * XSTR + xcol + f * 4) * 4,
                   Xbase + (size_t)xrow * HD + xcol + f * 4);
    for (int idx = tid; idx < 320; idx += 256) {
        int r = idx >> 3, f = idx & 7;
        cp_async16(wh_u + (uint32_t)(r * XSTR + f * 4) * 4,
                   g_cwH + (size_t)r * HD + f * 4);
        cp_async16(wl_u + (uint32_t)(r * XSTR + f * 4) * 4,
                   g_cwL + (size_t)r * HD + f * 4);
    }
    CP_COMMIT();

    float acc[5][4];
    #pragma unroll
    for (int ni = 0; ni < 5; ni++)
        #pragma unroll
        for (int q = 0; q < 4; q++) acc[ni][q] = 0.f;

    for (int kc = 0; kc < 24; kc++) {
        const int buf = kc & 1;
        if (kc + 1 < 24) {
            const int nb = (kc + 1) & 1;
            #pragma unroll
            for (int f = 0; f < 4; f++)
                cp_async16(xs_u + (uint32_t)(nb * XS_TILE + xrow * XSTR + xcol + f * 4) * 4,
                           Xbase + (size_t)xrow * HD + (kc + 1) * 32 + xcol + f * 4);
            for (int idx = tid; idx < 320; idx += 256) {
                int r = idx >> 3, f = idx & 7;
                cp_async16(wh_u + (uint32_t)(nb * WS_TILE + r * XSTR + f * 4) * 4,
                           g_cwH + (size_t)r * HD + (kc + 1) * 32 + f * 4);
                cp_async16(wl_u + (uint32_t)(nb * WS_TILE + r * XSTR + f * 4) * 4,
                           g_cwL + (size_t)r * HD + (kc + 1) * 32 + f * 4);
            }
            CP_COMMIT();
            CP_WAIT(1);
        } else {
            CP_WAIT(0);
        }
        __syncthreads();

        const float* Xb  = Xs + buf * XS_TILE;
        const float* Whb = Wh + buf * WS_TILE;
        const float* Wlb = Wl + buf * WS_TILE;
        #pragma unroll
        for (int ks = 0; ks < 4; ks++) {
            const int k8 = ks * 8;
            const int rb = w * 16 + g;
            uint32_t ah[4], al[4];
            {
                float x0 = Xb[rb * XSTR + k8 + tg];
                float x1 = Xb[(rb + 8) * XSTR + k8 + tg];
                float x2 = Xb[rb * XSTR + k8 + tg + 4];
                float x3 = Xb[(rb + 8) * XSTR + k8 + tg + 4];
                ah[0] = cvt_tf32(x0);
                ah[1] = cvt_tf32(x1);
                ah[2] = cvt_tf32(x2);
                ah[3] = cvt_tf32(x3);
                al[0] = cvt_tf32(x0 - __uint_as_float(ah[0]));
                al[1] = cvt_tf32(x1 - __uint_as_float(ah[1]));
                al[2] = cvt_tf32(x2 - __uint_as_float(ah[2]));
                al[3] = cvt_tf32(x3 - __uint_as_float(ah[3]));
            }
            #pragma unroll
            for (int ni = 0; ni < 5; ni++) {
                int ro = (ni * 8 + g) * XSTR + k8 + tg;
                uint32_t bh0 = __float_as_uint(Whb[ro]);
                uint32_t bh1 = __float_as_uint(Whb[ro + 4]);
                uint32_t bl0 = __float_as_uint(Wlb[ro]);
                uint32_t bl1 = __float_as_uint(Wlb[ro + 4]);
                mma_tf32(acc[ni], al, bh0, bh1);
                mma_tf32(acc[ni], ah, bl0, bl1);
                mma_tf32(acc[ni], ah, bh0, bh1);
            }
        }
        __syncthreads();
    }

    #pragma unroll
    for (int ni = 0; ni < 5; ni++)
        #pragma unroll
        for (int q = 0; q < 4; q++) {
            int r = w * 16 + g + ((q >= 2) ? 8 : 0);
            int t = ni * 8 + tg * 2 + (q & 1);
            if (t < TT) {
                float lg = fmaxf(acc[ni][q] + td_s[r] * zc_s[t]
                                 + lc_s[t] + cb_s[t], 0.f);
                Gs[r * 35 + t] = lg;
                long gtok = (long)n * SQ + r;
                out[LOGITS_OFF + (gtok + 1) * TT + t] = lg;
                if (gtok == 0)        out[LOGITS_OFF + t] = lg;
                if (gtok == NTOK - 1) out[LOGITS_OFF + (long)(NTOK + 1) * TT + t] = lg;
            }
        }
    __syncthreads();

    if (tid < SQ) {
        const int r = tid;
        const long gtok = (long)n * SQ + r;
        const int lbl = labels[gtok];
        const bool valid = (lbl != pad);
        const float* Lr = &Gs[r * 35];

        float mx = Lr[0]; int am = 0;
        #pragma unroll
        for (int t = 1; t < TT; t++) { float l = Lr[t]; if (l > mx) { mx = l; am = t; } }
        float se = 0.f;
        #pragma unroll
        for (int t = 0; t < TT; t++) se += __expf(Lr[t] - mx);
        float lse = mx + logf(se);
        float sy = Lr[lbl];
        float so = -1e30f;
        #pragma unroll
        for (int t = 0; t < TT; t++) if (t != lbl) so = fmaxf(so, Lr[t]);

        float hinge = valid ? fmaxf(0.f, 1.f + so - sy) : 0.f;
        float nll   = valid ? (lse - sy) : 0.f;
        float nv    = valid ? 1.f : 0.f;

        g_pred[gtok] = am;
        out[LBL_OFF + gtok + 1] = (float)lbl;
        if (gtok == 0)        out[LBL_OFF] = (float)lbl;
        if (gtok == NTOK - 1) out[LBL_OFF + NTOK + 1] = (float)lbl;

        if (r == SQ - 2) atomicAdd(&g_histApred[am], 1.f);
        if (r == SQ - 1) atomicAdd(&g_histBpred[am], 1.f);

        for (int o = 16; o > 0; o >>= 1) {
            hinge += __shfl_xor_sync(~0u, hinge, o);
            nll   += __shfl_xor_sync(~0u, nll, o);
            nv    += __shfl_xor_sync(~0u, nv, o);
        }
        if (lane == 0) { rh[w] = hinge; rn[w] = nll; rv[w] = nv; }
    }
    __syncthreads();
    if (tid == 0) {
        float H = 0, N2 = 0, V = 0;
        for (int q = 0; q < 4; q++) { H += rh[q]; N2 += rn[q]; V += rv[q]; }
        atomicAdd(&g_red[0], H);
        atomicAdd(&g_red[1], N2);
        atomicAdd(&g_red[4], V);
    }
}

// ============ K6: energy local dots + ste (float4 vectorized) =============
__global__ __launch_bounds__(192) void k6_energy_ste(
    const float* __restrict__ X, const float* __restrict__ ml,
    const float* __restrict__ linb, const int* __restrict__ labels,
    const int* __restrict__ padp, float* __restrict__ out)
{
    __shared__ int lbl_s[SQ], pred_s[SQ];
    __shared__ float td_s[SQ];
    __shared__ float s_cnt, s_tdm, s_dL, s_dP;
    const int n = blockIdx.x, tid = threadIdx.x;
    const int lane = tid & 31;
    const int pad = padp[0];

    if (tid == 0) { s_cnt = 0.f; s_tdm = 0.f; s_dL = 0.f; s_dP = 0.f; }
    if (tid < SQ) {
        lbl_s[tid]  = labels[n * SQ + tid];
        pred_s[tid] = g_pred[n * SQ + tid];
        td_s[tid]   = g_td[n * SQ + tid];
    }
    __syncthreads();

    float cnt_p = 0.f, tdm_p = 0.f, dotL = 0.f, dotP = 0.f;
    if (tid < SQ) {
        int l = lbl_s[tid], p = pred_s[tid];
        float m = (p != pad) ? 1.f : 0.f;
        cnt_p = m; tdm_p = m * td_s[tid];
        dotL = td_s[tid] * g_zml[n * TT + l] + g_lml[l];
        dotP = td_s[tid] * g_zml[n * TT + p] + g_lml[p];
    }

    const int h0 = tid * 4;
    const float* Xn = X + (size_t)n * SQ * HD;
    float st0 = 0.f, st1 = 0.f, st2 = 0.f, st3 = 0.f;
    for (int s = 0; s < SQ; s++) {
        float4 x4 = *(const float4*)(Xn + (size_t)s * HD + h0);
        int l = lbl_s[s], p = pred_s[s];
        float4 mL = *(const float4*)(ml + (size_t)l * HD + h0);
        float4 mP = *(const float4*)(ml + (size_t)p * HD + h0);
        dotL += x4.x * mL.x + x4.y * mL.y + x4.z * mL.z + x4.w * mL.w;
        dotP += x4.x * mP.x + x4.y * mP.y + x4.z * mP.z + x4.w * mP.w;
        if (p != pad) { st0 += x4.x; st1 += x4.y; st2 += x4.z; st3 += x4.w; }
    }

    for (int o = 16; o > 0; o >>= 1) {
        cnt_p += __shfl_xor_sync(~0u, cnt_p, o);
        tdm_p += __shfl_xor_sync(~0u, tdm_p, o);
        dotL  += __shfl_xor_sync(~0u, dotL, o);
        dotP  += __shfl_xor_sync(~0u, dotP, o);
    }
    if (lane == 0) {
        atomicAdd(&s_cnt, cnt_p);
        atomicAdd(&s_tdm, tdm_p);
        atomicAdd(&s_dL, dotL);
        atomicAdd(&s_dP, dotP);
    }
    __syncthreads();
    if (tid == 0) {
        atomicAdd(&g_red[2], s_dL);
        atomicAdd(&g_red[3], s_dP);
    }

    const float cnt = s_cnt, tdm = s_tdm;
    float o0 = 0.f, o1 = 0.f, o2 = 0.f, o3 = 0.f;
    if (cnt > 0.f) {
        const float* zp = g_z + (size_t)n * HD + h0;
        const float* lp = linb + h0;
        float inv = 1.f / cnt;
        o0 = (st0 + tdm * zp[0] + cnt * lp[0]) * inv;
        o1 = (st1 + tdm * zp[1] + cnt * lp[1]) * inv;
        o2 = (st2 + tdm * zp[2] + cnt * lp[2]) * inv;
        o3 = (st3 + tdm * zp[3] + cnt * lp[3]) * inv;
    }
    float* op = out + STE_OFF + (size_t)n * HD + h0;
    op[0] = o0; op[1] = o1; op[2] = o2; op[3] = o3;
}

// ============ K7: finalize scalar loss =====================================
__global__ void k7_final(const float* __restrict__ mlab, float* __restrict__ out)
{
    __shared__ float s1[TT], s2[TT];
    int t = threadIdx.x;
    if (t < TT) {
        float rl = 0.f, rp = 0.f;
        for (int u = 0; u < TT; u++) {
            float mv = mlab[t * TT + u];
            rl += mv * g_histBlbl[u];
            rp += mv * g_histBpred[u];
        }
        s1[t] = g_histAlbl[t] * rl;
        s2[t] = g_histApred[t] * rp;
    }
    __syncthreads();
    if (t == 0) {
        float labL = 0.f, labP = 0.f;
        for (int u = 0; u < TT; u++) { labL += s1[u]; labP += s2[u]; }
        float nv = fmaxf(g_red[4], 1.f);
        float hinge = g_red[0] / nv;
        float ce = g_red[1] / nv;
        float El = g_red[2] + labL;
        float Ep = g_red[3] + labP;
        float lte = fmaxf(0.f, hinge + El - Ep);
        out[0] = 1.0f * lte + 0.5f * ce;
    }
}

extern "C" void kernel_launch(void* const* d_in, const int* in_sizes, int n_in,
                              void* d_out, int out_size)
{
    const float* X      = (const float*)d_in[0];
    const int*   labels = (const int*)  d_in[1];
    const int*   padp   = (const int*)  d_in[4];
    const float* Ww     = (const float*)d_in[6];
    const float* Wb     = (const float*)d_in[7];
    const float* vw     = (const float*)d_in[8];
    const float* clsw   = (const float*)d_in[10];
    const float* clsb   = (const float*)d_in[11];
    const float* ml     = (const float*)d_in[12];
    const float* mlab   = (const float*)d_in[13];
    const float* lw     = (const float*)d_in[14];
    const float* linb   = (const float*)d_in[15];
    float* out = (float*)d_out;
    (void)in_sizes; (void)n_in; (void)out_size;

    const int k1_smem = 4 * TILE_BF * 2;                       // 73728 bytes
    const int k5_smem = (2 * XS_TILE + 4 * WS_TILE) * 4;       // 48384 bytes
    cudaFuncSetAttribute(k1_mma, cudaFuncAttributeMaxDynamicSharedMemorySize, k1_smem);
    cudaFuncSetAttribute(k5_logits, cudaFuncAttributeMaxDynamicSharedMemorySize, k5_smem);

    c1_cvt<<<12288, 512>>>(X);
    c2_wt<<<dim3(24, 24), dim3(32, 8)>>>(Ww);
    c3_mlt<<<102, 256>>>(ml);
    c4_cwt<<<120, 256>>>(clsw);
    k1_mma<<<dim3(NMEN, 6), 256, k1_smem>>>(Wb, vw);
    k2_softmax_head<<<NMEN, 192>>>();
    k3_z<<<dim3(64, 3), 256>>>(lw);
    k4_small<<<129, 272>>>(clsw, linb, labels);
    k5_logits<<<NMEN, 256, k5_smem>>>(X, clsb, labels, padp, out);
    k6_energy_ste<<<NMEN, 192>>>(X, ml, linb, labels, padp, out);
    k7_final<<<1, 64>>>(mlab, out);
}